// round 3
// baseline (speedup 1.0000x reference)
#include <cuda_runtime.h>
#include <math.h>
#include <float.h>

#define N_SEQ 1024
#define DIM   1024
#define HEADS 16
#define KV_HEADS 4
#define DH    64
#define BS    32
#define NUM_SEL 8
#define W_BLK 32          // N_SEQ / BS
#define GQ    4           // HEADS / KV_HEADS
#define CDIM  2048        // BS*DH
#define HID   2048
#define QKV_COLS 1536     // (HEADS + 2*KV_HEADS) * DH
#define SCALE 0.125f      // DH^-0.5
#define NSEL1 9           // NUM_SEL + 1
#define JTOT  288         // NSEL1 * BS
#define CW    33          // MEM + W_BLK

// ---------------- scratch (device globals; no allocation allowed) ----------
__device__ float g_x[N_SEQ*DIM];
__device__ float g_qkv[N_SEQ*QKV_COLS];
__device__ float g_kpe[KV_HEADS*W_BLK*CDIM];
__device__ float g_vpe[KV_HEADS*W_BLK*CDIM];
__device__ float g_hk[KV_HEADS*W_BLK*HID];
__device__ float g_hv[KV_HEADS*W_BLK*HID];
__device__ float g_ckm[KV_HEADS*W_BLK*DH];
__device__ float g_cvm[KV_HEADS*W_BLK*DH];
__device__ float g_csim[HEADS*N_SEQ*CW];
__device__ float g_cout[N_SEQ*HEADS*DH];
__device__ float g_fout[N_SEQ*HEADS*DH];
__device__ int   g_selidx[KV_HEADS*N_SEQ*NSEL1];
__device__ int   g_selmask[KV_HEADS*N_SEQ*NSEL1];
__device__ float g_gates[N_SEQ*2*HEADS];
__device__ float g_comb[N_SEQ*HEADS*DH];

// ---------------- helpers ----------------
__device__ __forceinline__ float warpMax(float v) {
    #pragma unroll
    for (int o = 16; o; o >>= 1) v = fmaxf(v, __shfl_xor_sync(0xffffffffu, v, o));
    return v;
}
__device__ __forceinline__ float warpSum(float v) {
    #pragma unroll
    for (int o = 16; o; o >>= 1) v += __shfl_xor_sync(0xffffffffu, v, o);
    return v;
}

// ---------------- RMSNorm: x = inp * rsqrt(mean(inp^2)+eps) * g ------------
__global__ void rmsnorm_kernel(const float* __restrict__ inp,
                               const float* __restrict__ gw) {
    int n = blockIdx.x;
    int t = threadIdx.x;
    const float* row = inp + n * DIM;
    float s = 0.f;
    for (int c = t; c < DIM; c += 256) { float v = row[c]; s += v * v; }
    s = warpSum(s);
    __shared__ float wbuf[8];
    int lane = t & 31, wid = t >> 5;
    if (lane == 0) wbuf[wid] = s;
    __syncthreads();
    if (t == 0) {
        float tot = 0.f;
        #pragma unroll
        for (int i = 0; i < 8; i++) tot += wbuf[i];
        wbuf[0] = rsqrtf(tot / (float)DIM + 1e-6f);
    }
    __syncthreads();
    float r = wbuf[0];
    float* xr = g_x + n * DIM;
    for (int c = t; c < DIM; c += 256) xr[c] = row[c] * r * gw[c];
}

// ---------------- generic SGEMM: C = act(A@B + bias) -----------------------
// A: M x K row-major, B: K x N row-major. BM=BN=64, BK=16, 256 threads.
// ACT: 0 = none, 1 = relu, 2 = sigmoid
template <int ACT>
__global__ void sgemm_kernel(const float* __restrict__ A,
                             const float* __restrict__ B,
                             const float* __restrict__ bias,
                             float* __restrict__ C,
                             int M, int N, int K) {
    __shared__ float As[16][65];
    __shared__ float Bs[16][64];
    int tid = threadIdx.x;
    int tx = tid & 15, ty = tid >> 4;
    int m0 = blockIdx.y * 64, n0 = blockIdx.x * 64;
    float acc[4][4];
    #pragma unroll
    for (int i = 0; i < 4; i++)
        #pragma unroll
        for (int j = 0; j < 4; j++) acc[i][j] = 0.f;

    for (int k0 = 0; k0 < K; k0 += 16) {
        #pragma unroll
        for (int i = 0; i < 4; i++) {
            int li = tid + i * 256;
            int r = li >> 4, c = li & 15;
            int gm = m0 + r, gk = k0 + c;
            As[c][r] = (gm < M) ? A[gm * K + gk] : 0.f;
        }
        #pragma unroll
        for (int i = 0; i < 4; i++) {
            int li = tid + i * 256;
            int kr = li >> 6, nc = li & 63;
            int gk = k0 + kr, gn = n0 + nc;
            Bs[kr][nc] = (gn < N) ? B[gk * N + gn] : 0.f;
        }
        __syncthreads();
        #pragma unroll
        for (int kk = 0; kk < 16; kk++) {
            float a[4], b[4];
            #pragma unroll
            for (int i = 0; i < 4; i++) a[i] = As[kk][ty * 4 + i];
            #pragma unroll
            for (int j = 0; j < 4; j++) b[j] = Bs[kk][tx * 4 + j];
            #pragma unroll
            for (int i = 0; i < 4; i++)
                #pragma unroll
                for (int j = 0; j < 4; j++) acc[i][j] += a[i] * b[j];
        }
        __syncthreads();
    }
    #pragma unroll
    for (int i = 0; i < 4; i++) {
        int row = m0 + ty * 4 + i;
        if (row >= M) continue;
        #pragma unroll
        for (int j = 0; j < 4; j++) {
            int col = n0 + tx * 4 + j;
            if (col >= N) continue;
            float v = acc[i][j];
            if (bias) v += bias[col];
            if (ACT == 1) v = fmaxf(v, 0.f);
            if (ACT == 2) v = 1.f / (1.f + expf(-v));
            C[row * N + col] = v;
        }
    }
}

// ---------------- build kpe / vpe blocks (KV*W, CDIM) ----------------------
__global__ void build_pe_kernel(const float* __restrict__ k_pos,
                                const float* __restrict__ v_pos) {
    int idx = blockIdx.x * 256 + threadIdx.x;   // < 128*2048
    int row = idx >> 11;
    int c = idx & 2047;
    int h = row >> 5, w = row & 31;
    int pos = c >> 6, d = c & 63;
    int n = w * BS + pos;
    const float* base = g_qkv + n * QKV_COLS + h * 64 + d;
    g_kpe[idx] = base[1024] + k_pos[(h * BS + pos) * DH + d];
    g_vpe[idx] = base[1280] + v_pos[(h * BS + pos) * DH + d];
}

// ---------------- compressed attention (pre-rotary q) ----------------------
// grid (N_SEQ, HEADS), 64 threads; writes g_csim (logits) and g_cout
__global__ void cattn_kernel(const float* __restrict__ mem_kv) {
    int n = blockIdx.x, h = blockIdx.y, kv = h >> 2;
    int t = threadIdx.x;
    __shared__ __align__(16) float qv[64];
    __shared__ float sims[CW];
    __shared__ float sinv;
    qv[t] = g_qkv[n * QKV_COLS + h * 64 + t];
    __syncthreads();
    if (t < CW) {
        const float* kp = (t == 0) ? (mem_kv + kv * DH)
                                   : (g_ckm + (kv * W_BLK + t - 1) * DH);
        const float4* kp4 = reinterpret_cast<const float4*>(kp);
        const float4* q4 = reinterpret_cast<const float4*>(qv);
        float acc = 0.f;
        #pragma unroll
        for (int d = 0; d < 16; d++) {
            float4 kk = kp4[d], qq = q4[d];
            acc += qq.x * kk.x + qq.y * kk.y + qq.z * kk.z + qq.w * kk.w;
        }
        acc *= SCALE;
        sims[t] = acc;
        g_csim[(h * N_SEQ + n) * CW + t] = acc;
    }
    __syncthreads();
    if (t == 0) {
        float m = -FLT_MAX;
        for (int j = 0; j < CW; j++) m = fmaxf(m, sims[j]);
        float Z = 0.f;
        for (int j = 0; j < CW; j++) { float e = expf(sims[j] - m); sims[j] = e; Z += e; }
        sinv = 1.f / Z;
    }
    __syncthreads();
    float inv = sinv;
    float acc = 0.f;
    for (int j = 0; j < CW; j++) {
        // mem_kv layout (2, KV_HEADS, MEM=1, DH): V half starts at KV_HEADS*DH = 256
        const float* vp = (j == 0) ? (mem_kv + KV_HEADS * DH + kv * DH)
                                   : (g_cvm + (kv * W_BLK + j - 1) * DH);
        acc += sims[j] * vp[t];
    }
    g_cout[n * (HEADS * DH) + h * DH + t] = acc * inv;
}

// ---------------- rotary in-place on q (cols 0..1023) and k (1024..1279) ---
__global__ void rotary_kernel() {
    int idx = blockIdx.x * 256 + threadIdx.x;   // < 1024*640
    int n = idx / 640;
    int p = idx - n * 640;
    int col = p * 2;
    int i = (col & 63) >> 1;
    float inv = powf(10000.f, -(float)i / 32.f);
    float ang = (float)n * inv;
    float cs = cosf(ang), sn = sinf(ang);
    float* ptr = g_qkv + n * QKV_COLS + col;
    float x0 = ptr[0], x1 = ptr[1];
    ptr[0] = x0 * cs - x1 * sn;
    ptr[1] = x1 * cs + x0 * sn;
}

// ---------------- top-k block selection (one thread per (kv,n)) ------------
__global__ void select_kernel() {
    int id = blockIdx.x * 256 + threadIdx.x;
    if (id >= KV_HEADS * N_SEQ) return;
    int kv = id >> 10, n = id & 1023;
    float imp[W_BLK];
    #pragma unroll
    for (int w = 0; w < W_BLK; w++) {
        float s = 0.f;
        #pragma unroll
        for (int g = 0; g < GQ; g++)
            s += g_csim[((kv * GQ + g) * N_SEQ + n) * CW + 1 + w];
        imp[w] = s * 0.25f;
    }
    float m = -1000.f;
    #pragma unroll
    for (int w = 0; w < W_BLK; w++) m = fmaxf(m, imp[w]);
    float Z = expf(-1000.f - m);
    #pragma unroll
    for (int w = 0; w < W_BLK; w++) Z += expf(imp[w] - m);
    int* si = g_selidx + id * NSEL1;
    int* sm = g_selmask + id * NSEL1;
    bool used[W_BLK];
    #pragma unroll
    for (int w = 0; w < W_BLK; w++) used[w] = false;
    for (int s = 0; s < NUM_SEL; s++) {
        int best = -1; float bv = -FLT_MAX;
        for (int w = 0; w < W_BLK; w++)
            if (!used[w] && imp[w] > bv) { bv = imp[w]; best = w; }
        used[best] = true;
        si[s] = best;
        sm[s] = (expf(bv - m) / Z > 1e-10f) ? 1 : 0;
    }
    si[NUM_SEL] = n >> 5;   // own block, always attended
    sm[NUM_SEL] = 1;
}

// ---------------- fine attention over 9 gathered blocks --------------------
// grid (N_SEQ, HEADS), 128 threads
__global__ void fattn_kernel() {
    int n = blockIdx.x, h = blockIdx.y, kv = h >> 2;
    int t = threadIdx.x;
    int lane = t & 31, wid = t >> 5;
    __shared__ __align__(16) float qv[64];
    __shared__ float sims[JTOT];
    __shared__ int sblk[NSEL1], smk[NSEL1];
    __shared__ float wbuf[4], wbuf2[4];
    if (t < 64) qv[t] = g_qkv[n * QKV_COLS + h * 64 + t];
    if (t < NSEL1) {
        sblk[t] = g_selidx[(kv * N_SEQ + n) * NSEL1 + t];
        smk[t]  = g_selmask[(kv * N_SEQ + n) * NSEL1 + t];
    }
    __syncthreads();
    const float4* q4 = reinterpret_cast<const float4*>(qv);
    for (int j = t; j < JTOT; j += 128) {
        int s = j >> 5, pos = j & 31;
        if (!smk[s]) { sims[j] = -FLT_MAX; continue; }
        const float* kp = g_qkv + (sblk[s] * BS + pos) * QKV_COLS + 1024 + kv * 64;
        const float4* kp4 = reinterpret_cast<const float4*>(kp);
        float acc = 0.f;
        #pragma unroll
        for (int d = 0; d < 16; d++) {
            float4 kk = kp4[d], qq = q4[d];
            acc += qq.x * kk.x + qq.y * kk.y + qq.z * kk.z + qq.w * kk.w;
        }
        sims[j] = acc * SCALE;
    }
    __syncthreads();
    float lm = -FLT_MAX;
    for (int j = t; j < JTOT; j += 128) lm = fmaxf(lm, sims[j]);
    lm = warpMax(lm);
    if (lane == 0) wbuf[wid] = lm;
    __syncthreads();
    float m = fmaxf(fmaxf(wbuf[0], wbuf[1]), fmaxf(wbuf[2], wbuf[3]));
    float lz = 0.f;
    for (int j = t; j < JTOT; j += 128) {
        float e = expf(sims[j] - m);
        sims[j] = e;
        lz += e;
    }
    lz = warpSum(lz);
    if (lane == 0) wbuf2[wid] = lz;
    __syncthreads();
    float inv = 1.f / (wbuf2[0] + wbuf2[1] + wbuf2[2] + wbuf2[3]);
    if (t < 64) {
        float acc = 0.f;
        #pragma unroll
        for (int s = 0; s < NSEL1; s++) {
            const float* vp = g_qkv + (sblk[s] * BS) * QKV_COLS + 1280 + kv * 64 + t;
            #pragma unroll
            for (int pos = 0; pos < BS; pos++)
                acc += sims[s * BS + pos] * vp[pos * QKV_COLS];
        }
        g_fout[n * (HEADS * DH) + h * DH + t] = acc * inv;
    }
}

// ---------------- gated combine --------------------------------------------
__global__ void combine_kernel() {
    int idx = blockIdx.x * 256 + threadIdx.x;   // < 1024*1024
    int n = idx >> 10;
    int c = idx & 1023;
    int h = c >> 6;
    float g0 = g_gates[n * (2 * HEADS) + 2 * h];
    float g1 = g_gates[n * (2 * HEADS) + 2 * h + 1];
    g_comb[idx] = g0 * g_cout[idx] + g1 * g_fout[idx];
}

// ---------------- launch ----------------------------------------------------
extern "C" void kernel_launch(void* const* d_in, const int* in_sizes, int n_in,
                              void* d_out, int out_size) {
    const float* inp    = (const float*)d_in[0];
    const float* g_norm = (const float*)d_in[1];
    const float* w_qkv  = (const float*)d_in[2];
    const float* mem_kv = (const float*)d_in[3];
    const float* k_pos  = (const float*)d_in[4];
    const float* v_pos  = (const float*)d_in[5];
    const float* k_w1   = (const float*)d_in[6];
    const float* k_b1   = (const float*)d_in[7];
    const float* k_w2   = (const float*)d_in[8];
    const float* k_b2   = (const float*)d_in[9];
    const float* v_w1   = (const float*)d_in[10];
    const float* v_b1   = (const float*)d_in[11];
    const float* v_w2   = (const float*)d_in[12];
    const float* v_b2   = (const float*)d_in[13];
    const float* gate_w = (const float*)d_in[14];
    const float* gate_b = (const float*)d_in[15];
    const float* w_out  = (const float*)d_in[16];
    float* out = (float*)d_out;

    float *px, *pqkv, *pkpe, *pvpe, *phk, *phv, *pckm, *pcvm, *pgates, *pcomb;
    cudaGetSymbolAddress((void**)&px,    g_x);
    cudaGetSymbolAddress((void**)&pqkv,  g_qkv);
    cudaGetSymbolAddress((void**)&pkpe,  g_kpe);
    cudaGetSymbolAddress((void**)&pvpe,  g_vpe);
    cudaGetSymbolAddress((void**)&phk,   g_hk);
    cudaGetSymbolAddress((void**)&phv,   g_hv);
    cudaGetSymbolAddress((void**)&pckm,  g_ckm);
    cudaGetSymbolAddress((void**)&pcvm,  g_cvm);
    cudaGetSymbolAddress((void**)&pgates, g_gates);
    cudaGetSymbolAddress((void**)&pcomb, g_comb);

    // 1. RMSNorm
    rmsnorm_kernel<<<N_SEQ, 256>>>(inp, g_norm);
    // 2. QKV projection: (1024,1024) @ (1024,1536)
    sgemm_kernel<0><<<dim3(QKV_COLS / 64, N_SEQ / 64), 256>>>(
        px, w_qkv, nullptr, pqkv, N_SEQ, QKV_COLS, DIM);
    // 3. positional-embedded block inputs
    build_pe_kernel<<<(KV_HEADS * W_BLK * CDIM) / 256, 256>>>(k_pos, v_pos);
    // 4/5. compress MLPs (relu hidden, linear out)
    sgemm_kernel<1><<<dim3(HID / 64, 2), 256>>>(pkpe, k_w1, k_b1, phk, 128, HID, CDIM);
    sgemm_kernel<1><<<dim3(HID / 64, 2), 256>>>(pvpe, v_w1, v_b1, phv, 128, HID, CDIM);
    sgemm_kernel<0><<<dim3(1, 2), 256>>>(phk, k_w2, k_b2, pckm, 128, DH, HID);
    sgemm_kernel<0><<<dim3(1, 2), 256>>>(phv, v_w2, v_b2, pcvm, 128, DH, HID);
    // 6. compressed attention (pre-rotary q), stores csim logits
    cattn_kernel<<<dim3(N_SEQ, HEADS), 64>>>(mem_kv);
    // 7. rotary on q,k in-place
    rotary_kernel<<<(N_SEQ * 640) / 256, 256>>>();
    // 8. block selection
    select_kernel<<<(KV_HEADS * N_SEQ) / 256, 256>>>();
    // 9. fine attention
    fattn_kernel<<<dim3(N_SEQ, HEADS), 128>>>();
    // 10. gates = sigmoid(x @ gate_w + gate_b)
    sgemm_kernel<2><<<dim3(1, N_SEQ / 64), 256>>>(px, gate_w, gate_b, pgates,
                                                  N_SEQ, 2 * HEADS, DIM);
    // 11. gated combine
    combine_kernel<<<(N_SEQ * HEADS * DH) / 256, 256>>>();
    // 12. output projection -> d_out
    sgemm_kernel<0><<<dim3(DIM / 64, N_SEQ / 64), 256>>>(
        pcomb, w_out, nullptr, out, N_SEQ, DIM, DIM);
}

// round 4
// speedup vs baseline: 2.0711x; 2.0711x over previous
#include <cuda_runtime.h>
#include <math.h>
#include <float.h>
#include <stdint.h>

#define N_SEQ 1024
#define DIM   1024
#define HEADS 16
#define KV_HEADS 4
#define DH    64
#define BS    32
#define NUM_SEL 8
#define W_BLK 32
#define GQ    4
#define CDIM  2048
#define HID   2048
#define QKV_COLS 1536
#define SCALE 0.125f
#define NSEL1 9
#define JTOT  288
#define CW    33

// ---------------- scratch ----------------
__device__ float g_x[N_SEQ*DIM];
__device__ float g_qkv[N_SEQ*QKV_COLS];
__device__ float g_kpe[KV_HEADS*W_BLK*CDIM];
__device__ float g_vpe[KV_HEADS*W_BLK*CDIM];
__device__ float g_hk[KV_HEADS*W_BLK*HID];
__device__ float g_hv[KV_HEADS*W_BLK*HID];
__device__ float g_ckm[KV_HEADS*W_BLK*DH];
__device__ float g_cvm[KV_HEADS*W_BLK*DH];
__device__ float g_csim[HEADS*N_SEQ*CW];
__device__ float g_cout[N_SEQ*HEADS*DH];
__device__ float g_fout[N_SEQ*HEADS*DH];
__device__ int   g_selidx[KV_HEADS*N_SEQ*NSEL1];
__device__ int   g_selmask[KV_HEADS*N_SEQ*NSEL1];
__device__ float g_gates[N_SEQ*2*HEADS];     // raw (pre-sigmoid) gate logits
__device__ float g_comb[N_SEQ*HEADS*DH];

// ---------------- helpers ----------------
__device__ __forceinline__ float warpMax(float v) {
    #pragma unroll
    for (int o = 16; o; o >>= 1) v = fmaxf(v, __shfl_xor_sync(0xffffffffu, v, o));
    return v;
}
__device__ __forceinline__ float warpSum(float v) {
    #pragma unroll
    for (int o = 16; o; o >>= 1) v += __shfl_xor_sync(0xffffffffu, v, o);
    return v;
}
__device__ __forceinline__ uint32_t f2tf32(float f) {
    uint32_t u;
    asm("cvt.rna.tf32.f32 %0, %1;" : "=r"(u) : "f"(f));
    return u;
}
__device__ __forceinline__ void split_tf32(float v, uint32_t& hi, uint32_t& lo) {
    hi = f2tf32(v);
    lo = f2tf32(v - __uint_as_float(hi));
}
__device__ __forceinline__ void mma_tf32(float* c, const uint32_t* a, const uint32_t* b) {
    asm volatile(
        "mma.sync.aligned.m16n8k8.row.col.f32.tf32.tf32.f32 "
        "{%0,%1,%2,%3},{%4,%5,%6,%7},{%8,%9},{%0,%1,%2,%3};"
        : "+f"(c[0]), "+f"(c[1]), "+f"(c[2]), "+f"(c[3])
        : "r"(a[0]), "r"(a[1]), "r"(a[2]), "r"(a[3]), "r"(b[0]), "r"(b[1]));
}

// ---------------- RMSNorm ----------------
__global__ void rmsnorm_kernel(const float* __restrict__ inp,
                               const float* __restrict__ gw) {
    int n = blockIdx.x;
    int t = threadIdx.x;
    const float* row = inp + n * DIM;
    float s = 0.f;
    for (int c = t; c < DIM; c += 256) { float v = row[c]; s += v * v; }
    s = warpSum(s);
    __shared__ float wbuf[8];
    int lane = t & 31, wid = t >> 5;
    if (lane == 0) wbuf[wid] = s;
    __syncthreads();
    if (t == 0) {
        float tot = 0.f;
        #pragma unroll
        for (int i = 0; i < 8; i++) tot += wbuf[i];
        wbuf[0] = rsqrtf(tot / (float)DIM + 1e-6f);
    }
    __syncthreads();
    float r = wbuf[0];
    float* xr = g_x + n * DIM;
    for (int c = t; c < DIM; c += 256) xr[c] = row[c] * r * gw[c];
}

// ---------------- tf32x3 tensor-core GEMM ----------------------------------
// C = act(A@B + bias), A: MxK row-major (M % 128 == 0, K % 16 == 0),
// B: KxN row-major. BM=128, BN=64, BK=16, 256 threads (8 warps, 4Mx2N).
// blockIdx.z = sel*S + split: sel picks (A0,B0,bias0,C0) vs (A1,...),
// split covers K-range [split*K/S, ...). ATOMIC: atomicAdd into pre-init C.
// RELUA: apply relu when loading A (deferred activation from prior stage).
template <int ACT, int ATOMIC, int RELUA>
__global__ void mma_gemm(const float* __restrict__ A0, const float* __restrict__ A1,
                         const float* __restrict__ B0, const float* __restrict__ B1,
                         const float* __restrict__ bias0, const float* __restrict__ bias1,
                         float* __restrict__ C0, float* __restrict__ C1,
                         int M, int N, int K, int S) {
    __shared__ float As[128][17];
    __shared__ float Bs[16][72];
    int z = blockIdx.z;
    int sel = z / S, sp = z - sel * S;
    const float* A = sel ? A1 : A0;
    const float* B = sel ? B1 : B0;
    const float* bias = sel ? bias1 : bias0;
    float* C = sel ? C1 : C0;
    int Kc = K / S;
    int kb = sp * Kc;

    int tid = threadIdx.x;
    int lane = tid & 31, warp = tid >> 5;
    int wm = warp & 3, wn = warp >> 2;
    int m0 = blockIdx.y * 128, n0 = blockIdx.x * 64;

    float acc[2][4][4];
    #pragma unroll
    for (int i = 0; i < 2; i++)
        #pragma unroll
        for (int j = 0; j < 4; j++)
            #pragma unroll
            for (int l = 0; l < 4; l++) acc[i][j][l] = 0.f;

    for (int k0 = kb; k0 < kb + Kc; k0 += 16) {
        // load A tile 128x16 (512 float4, 2 per thread)
        #pragma unroll
        for (int i = 0; i < 2; i++) {
            int q = tid + i * 256;
            int r = q >> 2, c4 = (q & 3) * 4;
            const float4 f = *reinterpret_cast<const float4*>(A + (m0 + r) * K + k0 + c4);
            float4 g = f;
            if (RELUA) {
                g.x = fmaxf(g.x, 0.f); g.y = fmaxf(g.y, 0.f);
                g.z = fmaxf(g.z, 0.f); g.w = fmaxf(g.w, 0.f);
            }
            As[r][c4 + 0] = g.x; As[r][c4 + 1] = g.y;
            As[r][c4 + 2] = g.z; As[r][c4 + 3] = g.w;
        }
        // load B tile 16x64 (1 float4 per thread)
        {
            int kr = tid >> 4, nc = (tid & 15) * 4;
            int gn = n0 + nc;
            float4 f = make_float4(0.f, 0.f, 0.f, 0.f);
            if (gn < N) f = *reinterpret_cast<const float4*>(B + (k0 + kr) * N + gn);
            Bs[kr][nc + 0] = f.x; Bs[kr][nc + 1] = f.y;
            Bs[kr][nc + 2] = f.z; Bs[kr][nc + 3] = f.w;
        }
        __syncthreads();
        #pragma unroll
        for (int ks = 0; ks < 2; ks++) {
            int kbase = ks * 8;
            uint32_t ahi[2][4], alo[2][4], bhi[4][2], blo[4][2];
            #pragma unroll
            for (int mt = 0; mt < 2; mt++) {
                int am = wm * 32 + mt * 16 + (lane >> 2);
                int c = kbase + (lane & 3);
                split_tf32(As[am][c],       ahi[mt][0], alo[mt][0]);
                split_tf32(As[am + 8][c],   ahi[mt][1], alo[mt][1]);
                split_tf32(As[am][c + 4],   ahi[mt][2], alo[mt][2]);
                split_tf32(As[am + 8][c + 4], ahi[mt][3], alo[mt][3]);
            }
            #pragma unroll
            for (int nt = 0; nt < 4; nt++) {
                int bn = wn * 32 + nt * 8 + (lane >> 2);
                int r = kbase + (lane & 3);
                split_tf32(Bs[r][bn],     bhi[nt][0], blo[nt][0]);
                split_tf32(Bs[r + 4][bn], bhi[nt][1], blo[nt][1]);
            }
            #pragma unroll
            for (int mt = 0; mt < 2; mt++)
                #pragma unroll
                for (int nt = 0; nt < 4; nt++) {
                    mma_tf32(acc[mt][nt], alo[mt], bhi[nt]);
                    mma_tf32(acc[mt][nt], ahi[mt], blo[nt]);
                    mma_tf32(acc[mt][nt], ahi[mt], bhi[nt]);
                }
        }
        __syncthreads();
    }

    // epilogue
    #pragma unroll
    for (int mt = 0; mt < 2; mt++) {
        int row = m0 + wm * 32 + mt * 16 + (lane >> 2);
        #pragma unroll
        for (int nt = 0; nt < 4; nt++) {
            int col = n0 + wn * 32 + nt * 8 + (lane & 3) * 2;
            if (col >= N) continue;
            float* a4 = acc[mt][nt];
            if (ATOMIC) {
                atomicAdd(&C[row * N + col],           a4[0]);
                atomicAdd(&C[row * N + col + 1],       a4[1]);
                atomicAdd(&C[(row + 8) * N + col],     a4[2]);
                atomicAdd(&C[(row + 8) * N + col + 1], a4[3]);
            } else {
                float b0 = bias ? bias[col] : 0.f;
                float b1 = bias ? bias[col + 1] : 0.f;
                float v0 = a4[0] + b0, v1 = a4[1] + b1;
                float v2 = a4[2] + b0, v3 = a4[3] + b1;
                if (ACT == 1) {
                    v0 = fmaxf(v0, 0.f); v1 = fmaxf(v1, 0.f);
                    v2 = fmaxf(v2, 0.f); v3 = fmaxf(v3, 0.f);
                }
                C[row * N + col] = v0;
                C[row * N + col + 1] = v1;
                C[(row + 8) * N + col] = v2;
                C[(row + 8) * N + col + 1] = v3;
            }
        }
    }
}

// ---------------- bias pre-init for split-K atomic targets ------------------
#define SEG1 (128*HID)            // hk
#define SEG2 (2*128*HID)          // hv
#define SEG3 (SEG2 + 128*DH)      // ckm
#define SEG4 (SEG2 + 2*128*DH)    // cvm
#define SEGT (SEG4 + N_SEQ*32)    // gates raw
__global__ void init_bias_kernel(const float* __restrict__ kb1, const float* __restrict__ vb1,
                                 const float* __restrict__ kb2, const float* __restrict__ vb2,
                                 const float* __restrict__ gb) {
    int idx = blockIdx.x * 256 + threadIdx.x;
    if (idx >= SEGT) return;
    if (idx < SEG1)      g_hk[idx] = kb1[idx & (HID - 1)];
    else if (idx < SEG2) g_hv[idx - SEG1] = vb1[idx & (HID - 1)];
    else if (idx < SEG3) g_ckm[idx - SEG2] = kb2[idx & (DH - 1)];
    else if (idx < SEG4) g_cvm[idx - SEG3] = vb2[idx & (DH - 1)];
    else                 g_gates[idx - SEG4] = gb[idx & 31];
}

// ---------------- compressed attention (pre-rotary q) ----------------------
__global__ void cattn_kernel(const float* __restrict__ mem_kv) {
    int n = blockIdx.x, h = blockIdx.y, kv = h >> 2;
    int t = threadIdx.x;
    __shared__ __align__(16) float qv[64];
    __shared__ float sims[CW];
    __shared__ float sinv;
    qv[t] = g_qkv[n * QKV_COLS + h * 64 + t];
    __syncthreads();
    if (t < CW) {
        const float* kp = (t == 0) ? (mem_kv + kv * DH)
                                   : (g_ckm + (kv * W_BLK + t - 1) * DH);
        const float4* kp4 = reinterpret_cast<const float4*>(kp);
        const float4* q4 = reinterpret_cast<const float4*>(qv);
        float acc = 0.f;
        #pragma unroll
        for (int d = 0; d < 16; d++) {
            float4 kk = kp4[d], qq = q4[d];
            acc += qq.x * kk.x + qq.y * kk.y + qq.z * kk.z + qq.w * kk.w;
        }
        acc *= SCALE;
        sims[t] = acc;
        g_csim[(h * N_SEQ + n) * CW + t] = acc;
    }
    __syncthreads();
    if (t == 0) {
        float m = -FLT_MAX;
        for (int j = 0; j < CW; j++) m = fmaxf(m, sims[j]);
        float Z = 0.f;
        for (int j = 0; j < CW; j++) { float e = expf(sims[j] - m); sims[j] = e; Z += e; }
        sinv = 1.f / Z;
    }
    __syncthreads();
    float inv = sinv;
    float acc = 0.f;
    for (int j = 0; j < CW; j++) {
        const float* vp = (j == 0) ? (mem_kv + KV_HEADS * DH + kv * DH)
                                   : (g_cvm + (kv * W_BLK + j - 1) * DH);
        acc += sims[j] * vp[t];
    }
    g_cout[n * (HEADS * DH) + h * DH + t] = acc * inv;
}

// ---------------- rotary in-place on q/k ------------------------------------
__global__ void rotary_kernel() {
    int idx = blockIdx.x * 256 + threadIdx.x;   // < 1024*640
    int n = idx / 640;
    int p = idx - n * 640;
    int col = p * 2;
    int i = (col & 63) >> 1;
    float inv = powf(10000.f, -(float)i / 32.f);
    float ang = (float)n * inv;
    float cs = cosf(ang), sn = sinf(ang);
    float* ptr = g_qkv + n * QKV_COLS + col;
    float x0 = ptr[0], x1 = ptr[1];
    ptr[0] = x0 * cs - x1 * sn;
    ptr[1] = x1 * cs + x0 * sn;
}

// ---------------- top-k block selection -------------------------------------
__global__ void select_kernel() {
    int id = blockIdx.x * 256 + threadIdx.x;
    if (id >= KV_HEADS * N_SEQ) return;
    int kv = id >> 10, n = id & 1023;
    float imp[W_BLK];
    #pragma unroll
    for (int w = 0; w < W_BLK; w++) {
        float s = 0.f;
        #pragma unroll
        for (int g = 0; g < GQ; g++)
            s += g_csim[((kv * GQ + g) * N_SEQ + n) * CW + 1 + w];
        imp[w] = s * 0.25f;
    }
    float m = -1000.f;
    #pragma unroll
    for (int w = 0; w < W_BLK; w++) m = fmaxf(m, imp[w]);
    float Z = expf(-1000.f - m);
    #pragma unroll
    for (int w = 0; w < W_BLK; w++) Z += expf(imp[w] - m);
    int* si = g_selidx + id * NSEL1;
    int* sm = g_selmask + id * NSEL1;
    bool used[W_BLK];
    #pragma unroll
    for (int w = 0; w < W_BLK; w++) used[w] = false;
    for (int s = 0; s < NUM_SEL; s++) {
        int best = -1; float bv = -FLT_MAX;
        for (int w = 0; w < W_BLK; w++)
            if (!used[w] && imp[w] > bv) { bv = imp[w]; best = w; }
        used[best] = true;
        si[s] = best;
        sm[s] = (expf(bv - m) / Z > 1e-10f) ? 1 : 0;
    }
    si[NUM_SEL] = n >> 5;
    sm[NUM_SEL] = 1;
}

// ---------------- fine attention ---------------------------------------------
__global__ void fattn_kernel() {
    int n = blockIdx.x, h = blockIdx.y, kv = h >> 2;
    int t = threadIdx.x;
    int lane = t & 31, wid = t >> 5;
    __shared__ __align__(16) float qv[64];
    __shared__ float sims[JTOT];
    __shared__ int sblk[NSEL1], smk[NSEL1];
    __shared__ float wbuf[4], wbuf2[4];
    if (t < 64) qv[t] = g_qkv[n * QKV_COLS + h * 64 + t];
    if (t < NSEL1) {
        sblk[t] = g_selidx[(kv * N_SEQ + n) * NSEL1 + t];
        smk[t]  = g_selmask[(kv * N_SEQ + n) * NSEL1 + t];
    }
    __syncthreads();
    const float4* q4 = reinterpret_cast<const float4*>(qv);
    for (int j = t; j < JTOT; j += 128) {
        int s = j >> 5, pos = j & 31;
        if (!smk[s]) { sims[j] = -FLT_MAX; continue; }
        const float* kp = g_qkv + (sblk[s] * BS + pos) * QKV_COLS + 1024 + kv * 64;
        const float4* kp4 = reinterpret_cast<const float4*>(kp);
        float acc = 0.f;
        #pragma unroll
        for (int d = 0; d < 16; d++) {
            float4 kk = kp4[d], qq = q4[d];
            acc += qq.x * kk.x + qq.y * kk.y + qq.z * kk.z + qq.w * kk.w;
        }
        sims[j] = acc * SCALE;
    }
    __syncthreads();
    float lm = -FLT_MAX;
    for (int j = t; j < JTOT; j += 128) lm = fmaxf(lm, sims[j]);
    lm = warpMax(lm);
    if (lane == 0) wbuf[wid] = lm;
    __syncthreads();
    float m = fmaxf(fmaxf(wbuf[0], wbuf[1]), fmaxf(wbuf[2], wbuf[3]));
    float lz = 0.f;
    for (int j = t; j < JTOT; j += 128) {
        float e = expf(sims[j] - m);
        sims[j] = e;
        lz += e;
    }
    lz = warpSum(lz);
    if (lane == 0) wbuf2[wid] = lz;
    __syncthreads();
    float inv = 1.f / (wbuf2[0] + wbuf2[1] + wbuf2[2] + wbuf2[3]);
    if (t < 64) {
        float acc = 0.f;
        #pragma unroll
        for (int s = 0; s < NSEL1; s++) {
            const float* vp = g_qkv + (sblk[s] * BS) * QKV_COLS + 1280 + kv * 64 + t;
            #pragma unroll
            for (int pos = 0; pos < BS; pos++)
                acc += sims[s * BS + pos] * vp[pos * QKV_COLS];
        }
        g_fout[n * (HEADS * DH) + h * DH + t] = acc * inv;
    }
}

// ---------------- build kpe / vpe -------------------------------------------
__global__ void build_pe_kernel(const float* __restrict__ k_pos,
                                const float* __restrict__ v_pos) {
    int idx = blockIdx.x * 256 + threadIdx.x;
    int row = idx >> 11;
    int c = idx & 2047;
    int h = row >> 5, w = row & 31;
    int pos = c >> 6, d = c & 63;
    int n = w * BS + pos;
    const float* base = g_qkv + n * QKV_COLS + h * 64 + d;
    g_kpe[idx] = base[1024] + k_pos[(h * BS + pos) * DH + d];
    g_vpe[idx] = base[1280] + v_pos[(h * BS + pos) * DH + d];
}

// ---------------- gated combine (applies sigmoid to raw gates) --------------
__global__ void combine_kernel() {
    int idx = blockIdx.x * 256 + threadIdx.x;
    int n = idx >> 10;
    int c = idx & 1023;
    int h = c >> 6;
    float r0 = g_gates[n * (2 * HEADS) + 2 * h];
    float r1 = g_gates[n * (2 * HEADS) + 2 * h + 1];
    float g0 = 1.f / (1.f + expf(-r0));
    float g1 = 1.f / (1.f + expf(-r1));
    g_comb[idx] = g0 * g_cout[idx] + g1 * g_fout[idx];
}

// ---------------- launch ------------------------------------------------------
extern "C" void kernel_launch(void* const* d_in, const int* in_sizes, int n_in,
                              void* d_out, int out_size) {
    const float* inp    = (const float*)d_in[0];
    const float* g_norm = (const float*)d_in[1];
    const float* w_qkv  = (const float*)d_in[2];
    const float* mem_kv = (const float*)d_in[3];
    const float* k_pos  = (const float*)d_in[4];
    const float* v_pos  = (const float*)d_in[5];
    const float* k_w1   = (const float*)d_in[6];
    const float* k_b1   = (const float*)d_in[7];
    const float* k_w2   = (const float*)d_in[8];
    const float* k_b2   = (const float*)d_in[9];
    const float* v_w1   = (const float*)d_in[10];
    const float* v_b1   = (const float*)d_in[11];
    const float* v_w2   = (const float*)d_in[12];
    const float* v_b2   = (const float*)d_in[13];
    const float* gate_w = (const float*)d_in[14];
    const float* gate_b = (const float*)d_in[15];
    const float* w_out  = (const float*)d_in[16];
    float* out = (float*)d_out;

    float *px, *pqkv, *pkpe, *pvpe, *phk, *phv, *pckm, *pcvm, *pgates, *pcomb;
    cudaGetSymbolAddress((void**)&px,     g_x);
    cudaGetSymbolAddress((void**)&pqkv,   g_qkv);
    cudaGetSymbolAddress((void**)&pkpe,   g_kpe);
    cudaGetSymbolAddress((void**)&pvpe,   g_vpe);
    cudaGetSymbolAddress((void**)&phk,    g_hk);
    cudaGetSymbolAddress((void**)&phv,    g_hv);
    cudaGetSymbolAddress((void**)&pckm,   g_ckm);
    cudaGetSymbolAddress((void**)&pcvm,   g_cvm);
    cudaGetSymbolAddress((void**)&pgates, g_gates);
    cudaGetSymbolAddress((void**)&pcomb,  g_comb);

    // 1. RMSNorm + bias pre-init for split-K targets
    rmsnorm_kernel<<<N_SEQ, 256>>>(inp, g_norm);
    init_bias_kernel<<<(SEGT + 255) / 256, 256>>>(k_b1, v_b1, k_b2, v_b2, gate_b);
    // 2. QKV projection: 1024x1536x1024
    mma_gemm<0, 0, 0><<<dim3(QKV_COLS / 64, N_SEQ / 128, 1), 256>>>(
        px, px, w_qkv, w_qkv, nullptr, nullptr, pqkv, pqkv, N_SEQ, QKV_COLS, DIM, 1);
    // 3. positional-embedded block inputs
    build_pe_kernel<<<(KV_HEADS * W_BLK * CDIM) / 256, 256>>>(k_pos, v_pos);
    // 4. MLP1 k+v dual, split-K=4, atomic into bias-init'd hidden (relu deferred)
    mma_gemm<0, 1, 0><<<dim3(HID / 64, 1, 2 * 4), 256>>>(
        pkpe, pvpe, k_w1, v_w1, nullptr, nullptr, phk, phv, 128, HID, CDIM, 4);
    // 5. MLP2 k+v dual, split-K=8, relu applied on A-load, atomic into bias-init'd out
    mma_gemm<0, 1, 1><<<dim3(1, 1, 2 * 8), 256>>>(
        phk, phv, k_w2, v_w2, nullptr, nullptr, pckm, pcvm, 128, DH, HID, 8);
    // 6. compressed attention (pre-rotary q)
    cattn_kernel<<<dim3(N_SEQ, HEADS), 64>>>(mem_kv);
    // 7. rotary
    rotary_kernel<<<(N_SEQ * 640) / 256, 256>>>();
    // 8. block selection
    select_kernel<<<(KV_HEADS * N_SEQ) / 256, 256>>>();
    // 9. fine attention
    fattn_kernel<<<dim3(N_SEQ, HEADS), 128>>>();
    // 10. gate logits, split-K=4, atomic into bias-init'd raw gates
    mma_gemm<0, 1, 0><<<dim3(1, N_SEQ / 128, 4), 256>>>(
        px, px, gate_w, gate_w, nullptr, nullptr, pgates, pgates, N_SEQ, 32, DIM, 4);
    // 11. gated combine (sigmoid applied here)
    combine_kernel<<<(N_SEQ * HEADS * DH) / 256, 256>>>();
    // 12. output projection -> d_out
    mma_gemm<0, 0, 0><<<dim3(DIM / 64, N_SEQ / 128, 1), 256>>>(
        pcomb, pcomb, w_out, w_out, nullptr, nullptr, out, out, N_SEQ, DIM, DIM, 1);
}

// round 5
// speedup vs baseline: 2.0741x; 1.0015x over previous
#include <cuda_runtime.h>
#include <math.h>
#include <float.h>
#include <stdint.h>

#define N_SEQ 1024
#define DIM   1024
#define HEADS 16
#define KV_HEADS 4
#define DH    64
#define BS    32
#define NUM_SEL 8
#define W_BLK 32
#define GQ    4
#define CDIM  2048
#define HID   2048
#define QKV_COLS 1536
#define SCALE 0.125f
#define NSEL1 9
#define JTOT  288
#define CW    33

// ---------------- scratch ----------------
__device__ float g_x[N_SEQ*DIM];
__device__ float g_qkv[N_SEQ*QKV_COLS];
__device__ float g_kpe[KV_HEADS*W_BLK*CDIM];
__device__ float g_vpe[KV_HEADS*W_BLK*CDIM];
__device__ float g_hk[KV_HEADS*W_BLK*HID];
__device__ float g_hv[KV_HEADS*W_BLK*HID];
__device__ float g_ckm[KV_HEADS*W_BLK*DH];
__device__ float g_cvm[KV_HEADS*W_BLK*DH];
__device__ float g_csim[HEADS*N_SEQ*CW];
__device__ float g_cout[N_SEQ*HEADS*DH];
__device__ float g_fout[N_SEQ*HEADS*DH];
__device__ int   g_selidx[KV_HEADS*N_SEQ*NSEL1];
__device__ int   g_selmask[KV_HEADS*N_SEQ*NSEL1];
__device__ float g_gates[N_SEQ*2*HEADS];     // raw (pre-sigmoid) gate logits
__device__ float g_comb[N_SEQ*HEADS*DH];

// ---------------- helpers ----------------
__device__ __forceinline__ float warpMax(float v) {
    #pragma unroll
    for (int o = 16; o; o >>= 1) v = fmaxf(v, __shfl_xor_sync(0xffffffffu, v, o));
    return v;
}
__device__ __forceinline__ float warpSum(float v) {
    #pragma unroll
    for (int o = 16; o; o >>= 1) v += __shfl_xor_sync(0xffffffffu, v, o);
    return v;
}
__device__ __forceinline__ uint32_t f2tf32(float f) {
    uint32_t u;
    asm("cvt.rna.tf32.f32 %0, %1;" : "=r"(u) : "f"(f));
    return u;
}
__device__ __forceinline__ void split_tf32(float v, uint32_t& hi, uint32_t& lo) {
    hi = f2tf32(v);
    lo = f2tf32(v - __uint_as_float(hi));
}
__device__ __forceinline__ void mma_tf32(float* c, const uint32_t* a, const uint32_t* b) {
    asm volatile(
        "mma.sync.aligned.m16n8k8.row.col.f32.tf32.tf32.f32 "
        "{%0,%1,%2,%3},{%4,%5,%6,%7},{%8,%9},{%0,%1,%2,%3};"
        : "+f"(c[0]), "+f"(c[1]), "+f"(c[2]), "+f"(c[3])
        : "r"(a[0]), "r"(a[1]), "r"(a[2]), "r"(a[3]), "r"(b[0]), "r"(b[1]));
}

// ---------------- RMSNorm ----------------
__global__ void rmsnorm_kernel(const float* __restrict__ inp,
                               const float* __restrict__ gw) {
    int n = blockIdx.x;
    int t = threadIdx.x;
    const float* row = inp + n * DIM;
    float s = 0.f;
    for (int c = t; c < DIM; c += 256) { float v = row[c]; s += v * v; }
    s = warpSum(s);
    __shared__ float wbuf[8];
    int lane = t & 31, wid = t >> 5;
    if (lane == 0) wbuf[wid] = s;
    __syncthreads();
    if (t == 0) {
        float tot = 0.f;
        #pragma unroll
        for (int i = 0; i < 8; i++) tot += wbuf[i];
        wbuf[0] = rsqrtf(tot / (float)DIM + 1e-6f);
    }
    __syncthreads();
    float r = wbuf[0];
    float* xr = g_x + n * DIM;
    for (int c = t; c < DIM; c += 256) xr[c] = row[c] * r * gw[c];
}

// ---------------- tf32x3 tensor-core GEMM ----------------------------------
// C = act(A@B + bias), A: MxK row-major (M % 128 == 0, K % 16 == 0),
// B: KxN row-major. BM=128, BN=64, BK=16, 256 threads (8 warps, 4Mx2N).
// blockIdx.z = sel*S + split: sel picks (A0,B0,bias0,C0) vs (A1,...),
// split covers K-range [split*K/S, ...). ATOMIC: atomicAdd into pre-init C.
// RELUA: apply relu when loading A (deferred activation from prior stage).
template <int ACT, int ATOMIC, int RELUA>
__global__ void mma_gemm(const float* __restrict__ A0, const float* __restrict__ A1,
                         const float* __restrict__ B0, const float* __restrict__ B1,
                         const float* __restrict__ bias0, const float* __restrict__ bias1,
                         float* __restrict__ C0, float* __restrict__ C1,
                         int M, int N, int K, int S) {
    __shared__ float As[128][17];
    __shared__ float Bs[16][72];
    int z = blockIdx.z;
    int sel = z / S, sp = z - sel * S;
    const float* A = sel ? A1 : A0;
    const float* B = sel ? B1 : B0;
    const float* bias = sel ? bias1 : bias0;
    float* C = sel ? C1 : C0;
    int Kc = K / S;
    int kb = sp * Kc;

    int tid = threadIdx.x;
    int lane = tid & 31, warp = tid >> 5;
    int wm = warp & 3, wn = warp >> 2;
    int m0 = blockIdx.y * 128, n0 = blockIdx.x * 64;

    float acc[2][4][4];
    #pragma unroll
    for (int i = 0; i < 2; i++)
        #pragma unroll
        for (int j = 0; j < 4; j++)
            #pragma unroll
            for (int l = 0; l < 4; l++) acc[i][j][l] = 0.f;

    for (int k0 = kb; k0 < kb + Kc; k0 += 16) {
        // load A tile 128x16 (512 float4, 2 per thread)
        #pragma unroll
        for (int i = 0; i < 2; i++) {
            int q = tid + i * 256;
            int r = q >> 2, c4 = (q & 3) * 4;
            const float4 f = *reinterpret_cast<const float4*>(A + (m0 + r) * K + k0 + c4);
            float4 g = f;
            if (RELUA) {
                g.x = fmaxf(g.x, 0.f); g.y = fmaxf(g.y, 0.f);
                g.z = fmaxf(g.z, 0.f); g.w = fmaxf(g.w, 0.f);
            }
            As[r][c4 + 0] = g.x; As[r][c4 + 1] = g.y;
            As[r][c4 + 2] = g.z; As[r][c4 + 3] = g.w;
        }
        // load B tile 16x64 (1 float4 per thread)
        {
            int kr = tid >> 4, nc = (tid & 15) * 4;
            int gn = n0 + nc;
            float4 f = make_float4(0.f, 0.f, 0.f, 0.f);
            if (gn < N) f = *reinterpret_cast<const float4*>(B + (k0 + kr) * N + gn);
            Bs[kr][nc + 0] = f.x; Bs[kr][nc + 1] = f.y;
            Bs[kr][nc + 2] = f.z; Bs[kr][nc + 3] = f.w;
        }
        __syncthreads();
        #pragma unroll
        for (int ks = 0; ks < 2; ks++) {
            int kbase = ks * 8;
            uint32_t ahi[2][4], alo[2][4], bhi[4][2], blo[4][2];
            #pragma unroll
            for (int mt = 0; mt < 2; mt++) {
                int am = wm * 32 + mt * 16 + (lane >> 2);
                int c = kbase + (lane & 3);
                split_tf32(As[am][c],       ahi[mt][0], alo[mt][0]);
                split_tf32(As[am + 8][c],   ahi[mt][1], alo[mt][1]);
                split_tf32(As[am][c + 4],   ahi[mt][2], alo[mt][2]);
                split_tf32(As[am + 8][c + 4], ahi[mt][3], alo[mt][3]);
            }
            #pragma unroll
            for (int nt = 0; nt < 4; nt++) {
                int bn = wn * 32 + nt * 8 + (lane >> 2);
                int r = kbase + (lane & 3);
                split_tf32(Bs[r][bn],     bhi[nt][0], blo[nt][0]);
                split_tf32(Bs[r + 4][bn], bhi[nt][1], blo[nt][1]);
            }
            #pragma unroll
            for (int mt = 0; mt < 2; mt++)
                #pragma unroll
                for (int nt = 0; nt < 4; nt++) {
                    mma_tf32(acc[mt][nt], alo[mt], bhi[nt]);
                    mma_tf32(acc[mt][nt], ahi[mt], blo[nt]);
                    mma_tf32(acc[mt][nt], ahi[mt], bhi[nt]);
                }
        }
        __syncthreads();
    }

    // epilogue
    #pragma unroll
    for (int mt = 0; mt < 2; mt++) {
        int row = m0 + wm * 32 + mt * 16 + (lane >> 2);
        #pragma unroll
        for (int nt = 0; nt < 4; nt++) {
            int col = n0 + wn * 32 + nt * 8 + (lane & 3) * 2;
            if (col >= N) continue;
            float* a4 = acc[mt][nt];
            if (ATOMIC) {
                atomicAdd(&C[row * N + col],           a4[0]);
                atomicAdd(&C[row * N + col + 1],       a4[1]);
                atomicAdd(&C[(row + 8) * N + col],     a4[2]);
                atomicAdd(&C[(row + 8) * N + col + 1], a4[3]);
            } else {
                float b0 = bias ? bias[col] : 0.f;
                float b1 = bias ? bias[col + 1] : 0.f;
                float v0 = a4[0] + b0, v1 = a4[1] + b1;
                float v2 = a4[2] + b0, v3 = a4[3] + b1;
                if (ACT == 1) {
                    v0 = fmaxf(v0, 0.f); v1 = fmaxf(v1, 0.f);
                    v2 = fmaxf(v2, 0.f); v3 = fmaxf(v3, 0.f);
                }
                C[row * N + col] = v0;
                C[row * N + col + 1] = v1;
                C[(row + 8) * N + col] = v2;
                C[(row + 8) * N + col + 1] = v3;
            }
        }
    }
}

// ---------------- bias pre-init for split-K atomic targets ------------------
#define SEG1 (128*HID)            // hk
#define SEG2 (2*128*HID)          // hv
#define SEG3 (SEG2 + 128*DH)      // ckm
#define SEG4 (SEG2 + 2*128*DH)    // cvm
#define SEGT (SEG4 + N_SEQ*32)    // gates raw
__global__ void init_bias_kernel(const float* __restrict__ kb1, const float* __restrict__ vb1,
                                 const float* __restrict__ kb2, const float* __restrict__ vb2,
                                 const float* __restrict__ gb) {
    int idx = blockIdx.x * 256 + threadIdx.x;
    if (idx >= SEGT) return;
    if (idx < SEG1)      g_hk[idx] = kb1[idx & (HID - 1)];
    else if (idx < SEG2) g_hv[idx - SEG1] = vb1[idx & (HID - 1)];
    else if (idx < SEG3) g_ckm[idx - SEG2] = kb2[idx & (DH - 1)];
    else if (idx < SEG4) g_cvm[idx - SEG3] = vb2[idx & (DH - 1)];
    else                 g_gates[idx - SEG4] = gb[idx & 31];
}

// ---------------- compressed attention (pre-rotary q) ----------------------
__global__ void cattn_kernel(const float* __restrict__ mem_kv) {
    int n = blockIdx.x, h = blockIdx.y, kv = h >> 2;
    int t = threadIdx.x;
    __shared__ __align__(16) float qv[64];
    __shared__ float sims[CW];
    __shared__ float sinv;
    qv[t] = g_qkv[n * QKV_COLS + h * 64 + t];
    __syncthreads();
    if (t < CW) {
        const float* kp = (t == 0) ? (mem_kv + kv * DH)
                                   : (g_ckm + (kv * W_BLK + t - 1) * DH);
        const float4* kp4 = reinterpret_cast<const float4*>(kp);
        const float4* q4 = reinterpret_cast<const float4*>(qv);
        float acc = 0.f;
        #pragma unroll
        for (int d = 0; d < 16; d++) {
            float4 kk = kp4[d], qq = q4[d];
            acc += qq.x * kk.x + qq.y * kk.y + qq.z * kk.z + qq.w * kk.w;
        }
        acc *= SCALE;
        sims[t] = acc;
        g_csim[(h * N_SEQ + n) * CW + t] = acc;
    }
    __syncthreads();
    if (t == 0) {
        float m = -FLT_MAX;
        for (int j = 0; j < CW; j++) m = fmaxf(m, sims[j]);
        float Z = 0.f;
        for (int j = 0; j < CW; j++) { float e = expf(sims[j] - m); sims[j] = e; Z += e; }
        sinv = 1.f / Z;
    }
    __syncthreads();
    float inv = sinv;
    float acc = 0.f;
    for (int j = 0; j < CW; j++) {
        const float* vp = (j == 0) ? (mem_kv + KV_HEADS * DH + kv * DH)
                                   : (g_cvm + (kv * W_BLK + j - 1) * DH);
        acc += sims[j] * vp[t];
    }
    g_cout[n * (HEADS * DH) + h * DH + t] = acc * inv;
}

// ---------------- rotary in-place on q/k ------------------------------------
__global__ void rotary_kernel() {
    int idx = blockIdx.x * 256 + threadIdx.x;   // < 1024*640
    int n = idx / 640;
    int p = idx - n * 640;
    int col = p * 2;
    int i = (col & 63) >> 1;
    float inv = powf(10000.f, -(float)i / 32.f);
    float ang = (float)n * inv;
    float cs = cosf(ang), sn = sinf(ang);
    float* ptr = g_qkv + n * QKV_COLS + col;
    float x0 = ptr[0], x1 = ptr[1];
    ptr[0] = x0 * cs - x1 * sn;
    ptr[1] = x1 * cs + x0 * sn;
}

// ---------------- top-k block selection -------------------------------------
__global__ void select_kernel() {
    int id = blockIdx.x * 256 + threadIdx.x;
    if (id >= KV_HEADS * N_SEQ) return;
    int kv = id >> 10, n = id & 1023;
    float imp[W_BLK];
    #pragma unroll
    for (int w = 0; w < W_BLK; w++) {
        float s = 0.f;
        #pragma unroll
        for (int g = 0; g < GQ; g++)
            s += g_csim[((kv * GQ + g) * N_SEQ + n) * CW + 1 + w];
        imp[w] = s * 0.25f;
    }
    float m = -1000.f;
    #pragma unroll
    for (int w = 0; w < W_BLK; w++) m = fmaxf(m, imp[w]);
    float Z = expf(-1000.f - m);
    #pragma unroll
    for (int w = 0; w < W_BLK; w++) Z += expf(imp[w] - m);
    int* si = g_selidx + id * NSEL1;
    int* sm = g_selmask + id * NSEL1;
    bool used[W_BLK];
    #pragma unroll
    for (int w = 0; w < W_BLK; w++) used[w] = false;
    for (int s = 0; s < NUM_SEL; s++) {
        int best = -1; float bv = -FLT_MAX;
        for (int w = 0; w < W_BLK; w++)
            if (!used[w] && imp[w] > bv) { bv = imp[w]; best = w; }
        used[best] = true;
        si[s] = best;
        sm[s] = (expf(bv - m) / Z > 1e-10f) ? 1 : 0;
    }
    si[NUM_SEL] = n >> 5;
    sm[NUM_SEL] = 1;
}

// ---------------- fine attention ---------------------------------------------
__global__ void fattn_kernel() {
    int n = blockIdx.x, h = blockIdx.y, kv = h >> 2;
    int t = threadIdx.x;
    int lane = t & 31, wid = t >> 5;
    __shared__ __align__(16) float qv[64];
    __shared__ float sims[JTOT];
    __shared__ int sblk[NSEL1], smk[NSEL1];
    __shared__ float wbuf[4], wbuf2[4];
    if (t < 64) qv[t] = g_qkv[n * QKV_COLS + h * 64 + t];
    if (t < NSEL1) {
        sblk[t] = g_selidx[(kv * N_SEQ + n) * NSEL1 + t];
        smk[t]  = g_selmask[(kv * N_SEQ + n) * NSEL1 + t];
    }
    __syncthreads();
    const float4* q4 = reinterpret_cast<const float4*>(qv);
    for (int j = t; j < JTOT; j += 128) {
        int s = j >> 5, pos = j & 31;
        if (!smk[s]) { sims[j] = -FLT_MAX; continue; }
        const float* kp = g_qkv + (sblk[s] * BS + pos) * QKV_COLS + 1024 + kv * 64;
        const float4* kp4 = reinterpret_cast<const float4*>(kp);
        float acc = 0.f;
        #pragma unroll
        for (int d = 0; d < 16; d++) {
            float4 kk = kp4[d], qq = q4[d];
            acc += qq.x * kk.x + qq.y * kk.y + qq.z * kk.z + qq.w * kk.w;
        }
        sims[j] = acc * SCALE;
    }
    __syncthreads();
    float lm = -FLT_MAX;
    for (int j = t; j < JTOT; j += 128) lm = fmaxf(lm, sims[j]);
    lm = warpMax(lm);
    if (lane == 0) wbuf[wid] = lm;
    __syncthreads();
    float m = fmaxf(fmaxf(wbuf[0], wbuf[1]), fmaxf(wbuf[2], wbuf[3]));
    float lz = 0.f;
    for (int j = t; j < JTOT; j += 128) {
        float e = expf(sims[j] - m);
        sims[j] = e;
        lz += e;
    }
    lz = warpSum(lz);
    if (lane == 0) wbuf2[wid] = lz;
    __syncthreads();
    float inv = 1.f / (wbuf2[0] + wbuf2[1] + wbuf2[2] + wbuf2[3]);
    if (t < 64) {
        float acc = 0.f;
        #pragma unroll
        for (int s = 0; s < NSEL1; s++) {
            const float* vp = g_qkv + (sblk[s] * BS) * QKV_COLS + 1280 + kv * 64 + t;
            #pragma unroll
            for (int pos = 0; pos < BS; pos++)
                acc += sims[s * BS + pos] * vp[pos * QKV_COLS];
        }
        g_fout[n * (HEADS * DH) + h * DH + t] = acc * inv;
    }
}

// ---------------- build kpe / vpe -------------------------------------------
__global__ void build_pe_kernel(const float* __restrict__ k_pos,
                                const float* __restrict__ v_pos) {
    int idx = blockIdx.x * 256 + threadIdx.x;
    int row = idx >> 11;
    int c = idx & 2047;
    int h = row >> 5, w = row & 31;
    int pos = c >> 6, d = c & 63;
    int n = w * BS + pos;
    const float* base = g_qkv + n * QKV_COLS + h * 64 + d;
    g_kpe[idx] = base[1024] + k_pos[(h * BS + pos) * DH + d];
    g_vpe[idx] = base[1280] + v_pos[(h * BS + pos) * DH + d];
}

// ---------------- gated combine (applies sigmoid to raw gates) --------------
__global__ void combine_kernel() {
    int idx = blockIdx.x * 256 + threadIdx.x;
    int n = idx >> 10;
    int c = idx & 1023;
    int h = c >> 6;
    float r0 = g_gates[n * (2 * HEADS) + 2 * h];
    float r1 = g_gates[n * (2 * HEADS) + 2 * h + 1];
    float g0 = 1.f / (1.f + expf(-r0));
    float g1 = 1.f / (1.f + expf(-r1));
    g_comb[idx] = g0 * g_cout[idx] + g1 * g_fout[idx];
}

// ---------------- launch ------------------------------------------------------
extern "C" void kernel_launch(void* const* d_in, const int* in_sizes, int n_in,
                              void* d_out, int out_size) {
    const float* inp    = (const float*)d_in[0];
    const float* g_norm = (const float*)d_in[1];
    const float* w_qkv  = (const float*)d_in[2];
    const float* mem_kv = (const float*)d_in[3];
    const float* k_pos  = (const float*)d_in[4];
    const float* v_pos  = (const float*)d_in[5];
    const float* k_w1   = (const float*)d_in[6];
    const float* k_b1   = (const float*)d_in[7];
    const float* k_w2   = (const float*)d_in[8];
    const float* k_b2   = (const float*)d_in[9];
    const float* v_w1   = (const float*)d_in[10];
    const float* v_b1   = (const float*)d_in[11];
    const float* v_w2   = (const float*)d_in[12];
    const float* v_b2   = (const float*)d_in[13];
    const float* gate_w = (const float*)d_in[14];
    const float* gate_b = (const float*)d_in[15];
    const float* w_out  = (const float*)d_in[16];
    float* out = (float*)d_out;

    float *px, *pqkv, *pkpe, *pvpe, *phk, *phv, *pckm, *pcvm, *pgates, *pcomb;
    cudaGetSymbolAddress((void**)&px,     g_x);
    cudaGetSymbolAddress((void**)&pqkv,   g_qkv);
    cudaGetSymbolAddress((void**)&pkpe,   g_kpe);
    cudaGetSymbolAddress((void**)&pvpe,   g_vpe);
    cudaGetSymbolAddress((void**)&phk,    g_hk);
    cudaGetSymbolAddress((void**)&phv,    g_hv);
    cudaGetSymbolAddress((void**)&pckm,   g_ckm);
    cudaGetSymbolAddress((void**)&pcvm,   g_cvm);
    cudaGetSymbolAddress((void**)&pgates, g_gates);
    cudaGetSymbolAddress((void**)&pcomb,  g_comb);

    // 1. RMSNorm + bias pre-init for split-K targets
    rmsnorm_kernel<<<N_SEQ, 256>>>(inp, g_norm);
    init_bias_kernel<<<(SEGT + 255) / 256, 256>>>(k_b1, v_b1, k_b2, v_b2, gate_b);
    // 2. QKV projection: 1024x1536x1024
    mma_gemm<0, 0, 0><<<dim3(QKV_COLS / 64, N_SEQ / 128, 1), 256>>>(
        px, px, w_qkv, w_qkv, nullptr, nullptr, pqkv, pqkv, N_SEQ, QKV_COLS, DIM, 1);
    // 3. positional-embedded block inputs
    build_pe_kernel<<<(KV_HEADS * W_BLK * CDIM) / 256, 256>>>(k_pos, v_pos);
    // 4. MLP1 k+v dual, split-K=4, atomic into bias-init'd hidden (relu deferred)
    mma_gemm<0, 1, 0><<<dim3(HID / 64, 1, 2 * 4), 256>>>(
        pkpe, pvpe, k_w1, v_w1, nullptr, nullptr, phk, phv, 128, HID, CDIM, 4);
    // 5. MLP2 k+v dual, split-K=8, relu applied on A-load, atomic into bias-init'd out
    mma_gemm<0, 1, 1><<<dim3(1, 1, 2 * 8), 256>>>(
        phk, phv, k_w2, v_w2, nullptr, nullptr, pckm, pcvm, 128, DH, HID, 8);
    // 6. compressed attention (pre-rotary q)
    cattn_kernel<<<dim3(N_SEQ, HEADS), 64>>>(mem_kv);
    // 7. rotary
    rotary_kernel<<<(N_SEQ * 640) / 256, 256>>>();
    // 8. block selection
    select_kernel<<<(KV_HEADS * N_SEQ) / 256, 256>>>();
    // 9. fine attention
    fattn_kernel<<<dim3(N_SEQ, HEADS), 128>>>();
    // 10. gate logits, split-K=4, atomic into bias-init'd raw gates
    mma_gemm<0, 1, 0><<<dim3(1, N_SEQ / 128, 4), 256>>>(
        px, px, gate_w, gate_w, nullptr, nullptr, pgates, pgates, N_SEQ, 32, DIM, 4);
    // 11. gated combine (sigmoid applied here)
    combine_kernel<<<(N_SEQ * HEADS * DH) / 256, 256>>>();
    // 12. output projection -> d_out
    mma_gemm<0, 0, 0><<<dim3(DIM / 64, N_SEQ / 128, 1), 256>>>(
        pcomb, pcomb, w_out, w_out, nullptr, nullptr, out, out, N_SEQ, DIM, DIM, 1);
}

// round 6
// speedup vs baseline: 2.0744x; 1.0001x over previous
#include <cuda_runtime.h>
#include <math.h>
#include <float.h>
#include <stdint.h>

#define N_SEQ 1024
#define DIM   1024
#define HEADS 16
#define KV_HEADS 4
#define DH    64
#define BS    32
#define NUM_SEL 8
#define W_BLK 32
#define GQ    4
#define CDIM  2048
#define HID   2048
#define QKV_COLS 1536
#define SCALE 0.125f
#define NSEL1 9
#define JTOT  288
#define CW    33

// ---------------- scratch ----------------
__device__ float g_x[N_SEQ*DIM];
__device__ float g_qkv[N_SEQ*QKV_COLS];
__device__ float g_kpe[KV_HEADS*W_BLK*CDIM];
__device__ float g_vpe[KV_HEADS*W_BLK*CDIM];
__device__ float g_hk[KV_HEADS*W_BLK*HID];
__device__ float g_hv[KV_HEADS*W_BLK*HID];
__device__ float g_ckm[KV_HEADS*W_BLK*DH];
__device__ float g_cvm[KV_HEADS*W_BLK*DH];
__device__ float g_csim[HEADS*N_SEQ*CW];
__device__ float g_cout[N_SEQ*HEADS*DH];
__device__ float g_fout[N_SEQ*HEADS*DH];
__device__ int   g_selidx[KV_HEADS*N_SEQ*NSEL1];
__device__ int   g_selmask[KV_HEADS*N_SEQ*NSEL1];
__device__ float g_gates[N_SEQ*2*HEADS];     // raw (pre-sigmoid) gate logits
__device__ float g_comb[N_SEQ*HEADS*DH];

// ---------------- helpers ----------------
__device__ __forceinline__ float warpMax(float v) {
    #pragma unroll
    for (int o = 16; o; o >>= 1) v = fmaxf(v, __shfl_xor_sync(0xffffffffu, v, o));
    return v;
}
__device__ __forceinline__ float warpSum(float v) {
    #pragma unroll
    for (int o = 16; o; o >>= 1) v += __shfl_xor_sync(0xffffffffu, v, o);
    return v;
}
__device__ __forceinline__ uint32_t f2tf32(float f) {
    uint32_t u;
    asm("cvt.rna.tf32.f32 %0, %1;" : "=r"(u) : "f"(f));
    return u;
}
__device__ __forceinline__ void split_tf32(float v, uint32_t& hi, uint32_t& lo) {
    hi = f2tf32(v);
    lo = f2tf32(v - __uint_as_float(hi));
}
__device__ __forceinline__ void mma_tf32(float* c, const uint32_t* a, const uint32_t* b) {
    asm volatile(
        "mma.sync.aligned.m16n8k8.row.col.f32.tf32.tf32.f32 "
        "{%0,%1,%2,%3},{%4,%5,%6,%7},{%8,%9},{%0,%1,%2,%3};"
        : "+f"(c[0]), "+f"(c[1]), "+f"(c[2]), "+f"(c[3])
        : "r"(a[0]), "r"(a[1]), "r"(a[2]), "r"(a[3]), "r"(b[0]), "r"(b[1]));
}

// ---------------- RMSNorm ----------------
__global__ void rmsnorm_kernel(const float* __restrict__ inp,
                               const float* __restrict__ gw) {
    int n = blockIdx.x;
    int t = threadIdx.x;
    const float* row = inp + n * DIM;
    float s = 0.f;
    for (int c = t; c < DIM; c += 256) { float v = row[c]; s += v * v; }
    s = warpSum(s);
    __shared__ float wbuf[8];
    int lane = t & 31, wid = t >> 5;
    if (lane == 0) wbuf[wid] = s;
    __syncthreads();
    if (t == 0) {
        float tot = 0.f;
        #pragma unroll
        for (int i = 0; i < 8; i++) tot += wbuf[i];
        wbuf[0] = rsqrtf(tot / (float)DIM + 1e-6f);
    }
    __syncthreads();
    float r = wbuf[0];
    float* xr = g_x + n * DIM;
    for (int c = t; c < DIM; c += 256) xr[c] = row[c] * r * gw[c];
}

// ---------------- tf32x3 tensor-core GEMM ----------------------------------
// C = act(A@B + bias), A: MxK row-major (M % 128 == 0, K % 16 == 0),
// B: KxN row-major. BM=128, BN=64, BK=16, 256 threads (8 warps, 4Mx2N).
// blockIdx.z = sel*S + split: sel picks (A0,B0,bias0,C0) vs (A1,...),
// split covers K-range [split*K/S, ...). ATOMIC: atomicAdd into pre-init C.
// RELUA: apply relu when loading A (deferred activation from prior stage).
template <int ACT, int ATOMIC, int RELUA>
__global__ void mma_gemm(const float* __restrict__ A0, const float* __restrict__ A1,
                         const float* __restrict__ B0, const float* __restrict__ B1,
                         const float* __restrict__ bias0, const float* __restrict__ bias1,
                         float* __restrict__ C0, float* __restrict__ C1,
                         int M, int N, int K, int S) {
    __shared__ float As[128][17];
    __shared__ float Bs[16][72];
    int z = blockIdx.z;
    int sel = z / S, sp = z - sel * S;
    const float* A = sel ? A1 : A0;
    const float* B = sel ? B1 : B0;
    const float* bias = sel ? bias1 : bias0;
    float* C = sel ? C1 : C0;
    int Kc = K / S;
    int kb = sp * Kc;

    int tid = threadIdx.x;
    int lane = tid & 31, warp = tid >> 5;
    int wm = warp & 3, wn = warp >> 2;
    int m0 = blockIdx.y * 128, n0 = blockIdx.x * 64;

    float acc[2][4][4];
    #pragma unroll
    for (int i = 0; i < 2; i++)
        #pragma unroll
        for (int j = 0; j < 4; j++)
            #pragma unroll
            for (int l = 0; l < 4; l++) acc[i][j][l] = 0.f;

    for (int k0 = kb; k0 < kb + Kc; k0 += 16) {
        // load A tile 128x16 (512 float4, 2 per thread)
        #pragma unroll
        for (int i = 0; i < 2; i++) {
            int q = tid + i * 256;
            int r = q >> 2, c4 = (q & 3) * 4;
            const float4 f = *reinterpret_cast<const float4*>(A + (m0 + r) * K + k0 + c4);
            float4 g = f;
            if (RELUA) {
                g.x = fmaxf(g.x, 0.f); g.y = fmaxf(g.y, 0.f);
                g.z = fmaxf(g.z, 0.f); g.w = fmaxf(g.w, 0.f);
            }
            As[r][c4 + 0] = g.x; As[r][c4 + 1] = g.y;
            As[r][c4 + 2] = g.z; As[r][c4 + 3] = g.w;
        }
        // load B tile 16x64 (1 float4 per thread)
        {
            int kr = tid >> 4, nc = (tid & 15) * 4;
            int gn = n0 + nc;
            float4 f = make_float4(0.f, 0.f, 0.f, 0.f);
            if (gn < N) f = *reinterpret_cast<const float4*>(B + (k0 + kr) * N + gn);
            Bs[kr][nc + 0] = f.x; Bs[kr][nc + 1] = f.y;
            Bs[kr][nc + 2] = f.z; Bs[kr][nc + 3] = f.w;
        }
        __syncthreads();
        #pragma unroll
        for (int ks = 0; ks < 2; ks++) {
            int kbase = ks * 8;
            uint32_t ahi[2][4], alo[2][4], bhi[4][2], blo[4][2];
            #pragma unroll
            for (int mt = 0; mt < 2; mt++) {
                int am = wm * 32 + mt * 16 + (lane >> 2);
                int c = kbase + (lane & 3);
                split_tf32(As[am][c],       ahi[mt][0], alo[mt][0]);
                split_tf32(As[am + 8][c],   ahi[mt][1], alo[mt][1]);
                split_tf32(As[am][c + 4],   ahi[mt][2], alo[mt][2]);
                split_tf32(As[am + 8][c + 4], ahi[mt][3], alo[mt][3]);
            }
            #pragma unroll
            for (int nt = 0; nt < 4; nt++) {
                int bn = wn * 32 + nt * 8 + (lane >> 2);
                int r = kbase + (lane & 3);
                split_tf32(Bs[r][bn],     bhi[nt][0], blo[nt][0]);
                split_tf32(Bs[r + 4][bn], bhi[nt][1], blo[nt][1]);
            }
            #pragma unroll
            for (int mt = 0; mt < 2; mt++)
                #pragma unroll
                for (int nt = 0; nt < 4; nt++) {
                    mma_tf32(acc[mt][nt], alo[mt], bhi[nt]);
                    mma_tf32(acc[mt][nt], ahi[mt], blo[nt]);
                    mma_tf32(acc[mt][nt], ahi[mt], bhi[nt]);
                }
        }
        __syncthreads();
    }

    // epilogue
    #pragma unroll
    for (int mt = 0; mt < 2; mt++) {
        int row = m0 + wm * 32 + mt * 16 + (lane >> 2);
        #pragma unroll
        for (int nt = 0; nt < 4; nt++) {
            int col = n0 + wn * 32 + nt * 8 + (lane & 3) * 2;
            if (col >= N) continue;
            float* a4 = acc[mt][nt];
            if (ATOMIC) {
                atomicAdd(&C[row * N + col],           a4[0]);
                atomicAdd(&C[row * N + col + 1],       a4[1]);
                atomicAdd(&C[(row + 8) * N + col],     a4[2]);
                atomicAdd(&C[(row + 8) * N + col + 1], a4[3]);
            } else {
                float b0 = bias ? bias[col] : 0.f;
                float b1 = bias ? bias[col + 1] : 0.f;
                float v0 = a4[0] + b0, v1 = a4[1] + b1;
                float v2 = a4[2] + b0, v3 = a4[3] + b1;
                if (ACT == 1) {
                    v0 = fmaxf(v0, 0.f); v1 = fmaxf(v1, 0.f);
                    v2 = fmaxf(v2, 0.f); v3 = fmaxf(v3, 0.f);
                }
                C[row * N + col] = v0;
                C[row * N + col + 1] = v1;
                C[(row + 8) * N + col] = v2;
                C[(row + 8) * N + col + 1] = v3;
            }
        }
    }
}

// ---------------- bias pre-init for split-K atomic targets ------------------
#define SEG1 (128*HID)            // hk
#define SEG2 (2*128*HID)          // hv
#define SEG3 (SEG2 + 128*DH)      // ckm
#define SEG4 (SEG2 + 2*128*DH)    // cvm
#define SEGT (SEG4 + N_SEQ*32)    // gates raw
__global__ void init_bias_kernel(const float* __restrict__ kb1, const float* __restrict__ vb1,
                                 const float* __restrict__ kb2, const float* __restrict__ vb2,
                                 const float* __restrict__ gb) {
    int idx = blockIdx.x * 256 + threadIdx.x;
    if (idx >= SEGT) return;
    if (idx < SEG1)      g_hk[idx] = kb1[idx & (HID - 1)];
    else if (idx < SEG2) g_hv[idx - SEG1] = vb1[idx & (HID - 1)];
    else if (idx < SEG3) g_ckm[idx - SEG2] = kb2[idx & (DH - 1)];
    else if (idx < SEG4) g_cvm[idx - SEG3] = vb2[idx & (DH - 1)];
    else                 g_gates[idx - SEG4] = gb[idx & 31];
}

// ---------------- compressed attention (pre-rotary q) ----------------------
__global__ void cattn_kernel(const float* __restrict__ mem_kv) {
    int n = blockIdx.x, h = blockIdx.y, kv = h >> 2;
    int t = threadIdx.x;
    __shared__ __align__(16) float qv[64];
    __shared__ float sims[CW];
    __shared__ float sinv;
    qv[t] = g_qkv[n * QKV_COLS + h * 64 + t];
    __syncthreads();
    if (t < CW) {
        const float* kp = (t == 0) ? (mem_kv + kv * DH)
                                   : (g_ckm + (kv * W_BLK + t - 1) * DH);
        const float4* kp4 = reinterpret_cast<const float4*>(kp);
        const float4* q4 = reinterpret_cast<const float4*>(qv);
        float acc = 0.f;
        #pragma unroll
        for (int d = 0; d < 16; d++) {
            float4 kk = kp4[d], qq = q4[d];
            acc += qq.x * kk.x + qq.y * kk.y + qq.z * kk.z + qq.w * kk.w;
        }
        acc *= SCALE;
        sims[t] = acc;
        g_csim[(h * N_SEQ + n) * CW + t] = acc;
    }
    __syncthreads();
    if (t == 0) {
        float m = -FLT_MAX;
        for (int j = 0; j < CW; j++) m = fmaxf(m, sims[j]);
        float Z = 0.f;
        for (int j = 0; j < CW; j++) { float e = expf(sims[j] - m); sims[j] = e; Z += e; }
        sinv = 1.f / Z;
    }
    __syncthreads();
    float inv = sinv;
    float acc = 0.f;
    for (int j = 0; j < CW; j++) {
        const float* vp = (j == 0) ? (mem_kv + KV_HEADS * DH + kv * DH)
                                   : (g_cvm + (kv * W_BLK + j - 1) * DH);
        acc += sims[j] * vp[t];
    }
    g_cout[n * (HEADS * DH) + h * DH + t] = acc * inv;
}

// ---------------- rotary in-place on q/k ------------------------------------
__global__ void rotary_kernel() {
    int idx = blockIdx.x * 256 + threadIdx.x;   // < 1024*640
    int n = idx / 640;
    int p = idx - n * 640;
    int col = p * 2;
    int i = (col & 63) >> 1;
    float inv = powf(10000.f, -(float)i / 32.f);
    float ang = (float)n * inv;
    float cs = cosf(ang), sn = sinf(ang);
    float* ptr = g_qkv + n * QKV_COLS + col;
    float x0 = ptr[0], x1 = ptr[1];
    ptr[0] = x0 * cs - x1 * sn;
    ptr[1] = x1 * cs + x0 * sn;
}

// ---------------- top-k block selection -------------------------------------
__global__ void select_kernel() {
    int id = blockIdx.x * 256 + threadIdx.x;
    if (id >= KV_HEADS * N_SEQ) return;
    int kv = id >> 10, n = id & 1023;
    float imp[W_BLK];
    #pragma unroll
    for (int w = 0; w < W_BLK; w++) {
        float s = 0.f;
        #pragma unroll
        for (int g = 0; g < GQ; g++)
            s += g_csim[((kv * GQ + g) * N_SEQ + n) * CW + 1 + w];
        imp[w] = s * 0.25f;
    }
    float m = -1000.f;
    #pragma unroll
    for (int w = 0; w < W_BLK; w++) m = fmaxf(m, imp[w]);
    float Z = expf(-1000.f - m);
    #pragma unroll
    for (int w = 0; w < W_BLK; w++) Z += expf(imp[w] - m);
    int* si = g_selidx + id * NSEL1;
    int* sm = g_selmask + id * NSEL1;
    bool used[W_BLK];
    #pragma unroll
    for (int w = 0; w < W_BLK; w++) used[w] = false;
    for (int s = 0; s < NUM_SEL; s++) {
        int best = -1; float bv = -FLT_MAX;
        for (int w = 0; w < W_BLK; w++)
            if (!used[w] && imp[w] > bv) { bv = imp[w]; best = w; }
        used[best] = true;
        si[s] = best;
        sm[s] = (expf(bv - m) / Z > 1e-10f) ? 1 : 0;
    }
    si[NUM_SEL] = n >> 5;
    sm[NUM_SEL] = 1;
}

// ---------------- fine attention ---------------------------------------------
__global__ void fattn_kernel() {
    int n = blockIdx.x, h = blockIdx.y, kv = h >> 2;
    int t = threadIdx.x;
    int lane = t & 31, wid = t >> 5;
    __shared__ __align__(16) float qv[64];
    __shared__ float sims[JTOT];
    __shared__ int sblk[NSEL1], smk[NSEL1];
    __shared__ float wbuf[4], wbuf2[4];
    if (t < 64) qv[t] = g_qkv[n * QKV_COLS + h * 64 + t];
    if (t < NSEL1) {
        sblk[t] = g_selidx[(kv * N_SEQ + n) * NSEL1 + t];
        smk[t]  = g_selmask[(kv * N_SEQ + n) * NSEL1 + t];
    }
    __syncthreads();
    const float4* q4 = reinterpret_cast<const float4*>(qv);
    for (int j = t; j < JTOT; j += 128) {
        int s = j >> 5, pos = j & 31;
        if (!smk[s]) { sims[j] = -FLT_MAX; continue; }
        const float* kp = g_qkv + (sblk[s] * BS + pos) * QKV_COLS + 1024 + kv * 64;
        const float4* kp4 = reinterpret_cast<const float4*>(kp);
        float acc = 0.f;
        #pragma unroll
        for (int d = 0; d < 16; d++) {
            float4 kk = kp4[d], qq = q4[d];
            acc += qq.x * kk.x + qq.y * kk.y + qq.z * kk.z + qq.w * kk.w;
        }
        sims[j] = acc * SCALE;
    }
    __syncthreads();
    float lm = -FLT_MAX;
    for (int j = t; j < JTOT; j += 128) lm = fmaxf(lm, sims[j]);
    lm = warpMax(lm);
    if (lane == 0) wbuf[wid] = lm;
    __syncthreads();
    float m = fmaxf(fmaxf(wbuf[0], wbuf[1]), fmaxf(wbuf[2], wbuf[3]));
    float lz = 0.f;
    for (int j = t; j < JTOT; j += 128) {
        float e = expf(sims[j] - m);
        sims[j] = e;
        lz += e;
    }
    lz = warpSum(lz);
    if (lane == 0) wbuf2[wid] = lz;
    __syncthreads();
    float inv = 1.f / (wbuf2[0] + wbuf2[1] + wbuf2[2] + wbuf2[3]);
    if (t < 64) {
        float acc = 0.f;
        #pragma unroll
        for (int s = 0; s < NSEL1; s++) {
            const float* vp = g_qkv + (sblk[s] * BS) * QKV_COLS + 1280 + kv * 64 + t;
            #pragma unroll
            for (int pos = 0; pos < BS; pos++)
                acc += sims[s * BS + pos] * vp[pos * QKV_COLS];
        }
        g_fout[n * (HEADS * DH) + h * DH + t] = acc * inv;
    }
}

// ---------------- build kpe / vpe -------------------------------------------
__global__ void build_pe_kernel(const float* __restrict__ k_pos,
                                const float* __restrict__ v_pos) {
    int idx = blockIdx.x * 256 + threadIdx.x;
    int row = idx >> 11;
    int c = idx & 2047;
    int h = row >> 5, w = row & 31;
    int pos = c >> 6, d = c & 63;
    int n = w * BS + pos;
    const float* base = g_qkv + n * QKV_COLS + h * 64 + d;
    g_kpe[idx] = base[1024] + k_pos[(h * BS + pos) * DH + d];
    g_vpe[idx] = base[1280] + v_pos[(h * BS + pos) * DH + d];
}

// ---------------- gated combine (applies sigmoid to raw gates) --------------
__global__ void combine_kernel() {
    int idx = blockIdx.x * 256 + threadIdx.x;
    int n = idx >> 10;
    int c = idx & 1023;
    int h = c >> 6;
    float r0 = g_gates[n * (2 * HEADS) + 2 * h];
    float r1 = g_gates[n * (2 * HEADS) + 2 * h + 1];
    float g0 = 1.f / (1.f + expf(-r0));
    float g1 = 1.f / (1.f + expf(-r1));
    g_comb[idx] = g0 * g_cout[idx] + g1 * g_fout[idx];
}

// ---------------- launch ------------------------------------------------------
extern "C" void kernel_launch(void* const* d_in, const int* in_sizes, int n_in,
                              void* d_out, int out_size) {
    const float* inp    = (const float*)d_in[0];
    const float* g_norm = (const float*)d_in[1];
    const float* w_qkv  = (const float*)d_in[2];
    const float* mem_kv = (const float*)d_in[3];
    const float* k_pos  = (const float*)d_in[4];
    const float* v_pos  = (const float*)d_in[5];
    const float* k_w1   = (const float*)d_in[6];
    const float* k_b1   = (const float*)d_in[7];
    const float* k_w2   = (const float*)d_in[8];
    const float* k_b2   = (const float*)d_in[9];
    const float* v_w1   = (const float*)d_in[10];
    const float* v_b1   = (const float*)d_in[11];
    const float* v_w2   = (const float*)d_in[12];
    const float* v_b2   = (const float*)d_in[13];
    const float* gate_w = (const float*)d_in[14];
    const float* gate_b = (const float*)d_in[15];
    const float* w_out  = (const float*)d_in[16];
    float* out = (float*)d_out;

    float *px, *pqkv, *pkpe, *pvpe, *phk, *phv, *pckm, *pcvm, *pgates, *pcomb;
    cudaGetSymbolAddress((void**)&px,     g_x);
    cudaGetSymbolAddress((void**)&pqkv,   g_qkv);
    cudaGetSymbolAddress((void**)&pkpe,   g_kpe);
    cudaGetSymbolAddress((void**)&pvpe,   g_vpe);
    cudaGetSymbolAddress((void**)&phk,    g_hk);
    cudaGetSymbolAddress((void**)&phv,    g_hv);
    cudaGetSymbolAddress((void**)&pckm,   g_ckm);
    cudaGetSymbolAddress((void**)&pcvm,   g_cvm);
    cudaGetSymbolAddress((void**)&pgates, g_gates);
    cudaGetSymbolAddress((void**)&pcomb,  g_comb);

    // 1. RMSNorm + bias pre-init for split-K targets
    rmsnorm_kernel<<<N_SEQ, 256>>>(inp, g_norm);
    init_bias_kernel<<<(SEGT + 255) / 256, 256>>>(k_b1, v_b1, k_b2, v_b2, gate_b);
    // 2. QKV projection: 1024x1536x1024
    mma_gemm<0, 0, 0><<<dim3(QKV_COLS / 64, N_SEQ / 128, 1), 256>>>(
        px, px, w_qkv, w_qkv, nullptr, nullptr, pqkv, pqkv, N_SEQ, QKV_COLS, DIM, 1);
    // 3. positional-embedded block inputs
    build_pe_kernel<<<(KV_HEADS * W_BLK * CDIM) / 256, 256>>>(k_pos, v_pos);
    // 4. MLP1 k+v dual, split-K=4, atomic into bias-init'd hidden (relu deferred)
    mma_gemm<0, 1, 0><<<dim3(HID / 64, 1, 2 * 4), 256>>>(
        pkpe, pvpe, k_w1, v_w1, nullptr, nullptr, phk, phv, 128, HID, CDIM, 4);
    // 5. MLP2 k+v dual, split-K=8, relu applied on A-load, atomic into bias-init'd out
    mma_gemm<0, 1, 1><<<dim3(1, 1, 2 * 8), 256>>>(
        phk, phv, k_w2, v_w2, nullptr, nullptr, pckm, pcvm, 128, DH, HID, 8);
    // 6. compressed attention (pre-rotary q)
    cattn_kernel<<<dim3(N_SEQ, HEADS), 64>>>(mem_kv);
    // 7. rotary
    rotary_kernel<<<(N_SEQ * 640) / 256, 256>>>();
    // 8. block selection
    select_kernel<<<(KV_HEADS * N_SEQ) / 256, 256>>>();
    // 9. fine attention
    fattn_kernel<<<dim3(N_SEQ, HEADS), 128>>>();
    // 10. gate logits, split-K=4, atomic into bias-init'd raw gates
    mma_gemm<0, 1, 0><<<dim3(1, N_SEQ / 128, 4), 256>>>(
        px, px, gate_w, gate_w, nullptr, nullptr, pgates, pgates, N_SEQ, 32, DIM, 4);
    // 11. gated combine (sigmoid applied here)
    combine_kernel<<<(N_SEQ * HEADS * DH) / 256, 256>>>();
    // 12. output projection -> d_out
    mma_gemm<0, 0, 0><<<dim3(DIM / 64, N_SEQ / 128, 1), 256>>>(
        pcomb, pcomb, w_out, w_out, nullptr, nullptr, out, out, N_SEQ, DIM, DIM, 1);
}

// round 8
// speedup vs baseline: 2.8723x; 1.3847x over previous
#include <cuda_runtime.h>
#include <math.h>
#include <float.h>
#include <stdint.h>

#define N_SEQ 1024
#define DIM   1024
#define HEADS 16
#define KV_HEADS 4
#define DH    64
#define BS    32
#define NUM_SEL 8
#define W_BLK 32
#define GQ    4
#define CDIM  2048
#define HID   2048
#define QKV_COLS 1536
#define SCALE 0.125f
#define NSEL1 9
#define JTOT  288
#define CW    33

// ---------------- scratch ----------------
__device__ float g_x[N_SEQ*DIM];
__device__ float g_qkv[N_SEQ*QKV_COLS];
__device__ float g_kpe[KV_HEADS*W_BLK*CDIM];
__device__ float g_vpe[KV_HEADS*W_BLK*CDIM];
__device__ float g_hk[KV_HEADS*W_BLK*HID];
__device__ float g_hv[KV_HEADS*W_BLK*HID];
__device__ float g_ckm[KV_HEADS*W_BLK*DH];
__device__ float g_cvm[KV_HEADS*W_BLK*DH];
__device__ float g_csim[HEADS*N_SEQ*CW];
__device__ float g_cout[N_SEQ*HEADS*DH];
__device__ float g_fout[N_SEQ*HEADS*DH];
__device__ int   g_selidx[KV_HEADS*N_SEQ*NSEL1];
__device__ int   g_selmask[KV_HEADS*N_SEQ*NSEL1];
__device__ float g_gates[N_SEQ*2*HEADS];
__device__ float g_comb[N_SEQ*HEADS*DH];

// ---------------- helpers ----------------
__device__ __forceinline__ float warpMax(float v) {
    #pragma unroll
    for (int o = 16; o; o >>= 1) v = fmaxf(v, __shfl_xor_sync(0xffffffffu, v, o));
    return v;
}
__device__ __forceinline__ float warpSum(float v) {
    #pragma unroll
    for (int o = 16; o; o >>= 1) v += __shfl_xor_sync(0xffffffffu, v, o);
    return v;
}
__device__ __forceinline__ uint32_t f2tf32(float f) {
    uint32_t u;
    asm("cvt.rna.tf32.f32 %0, %1;" : "=r"(u) : "f"(f));
    return u;
}
__device__ __forceinline__ void split_tf32(float v, uint32_t& hi, uint32_t& lo) {
    hi = f2tf32(v);
    lo = f2tf32(v - __uint_as_float(hi));
}
__device__ __forceinline__ void mma_tf32(float* c, const uint32_t* a, const uint32_t* b) {
    asm volatile(
        "mma.sync.aligned.m16n8k8.row.col.f32.tf32.tf32.f32 "
        "{%0,%1,%2,%3},{%4,%5,%6,%7},{%8,%9},{%0,%1,%2,%3};"
        : "+f"(c[0]), "+f"(c[1]), "+f"(c[2]), "+f"(c[3])
        : "r"(a[0]), "r"(a[1]), "r"(a[2]), "r"(a[3]), "r"(b[0]), "r"(b[1]));
}

// ---------------- RMSNorm ----------------
__global__ void rmsnorm_kernel(const float* __restrict__ inp,
                               const float* __restrict__ gw) {
    int n = blockIdx.x;
    int t = threadIdx.x;
    const float* row = inp + n * DIM;
    float s = 0.f;
    for (int c = t; c < DIM; c += 256) { float v = row[c]; s += v * v; }
    s = warpSum(s);
    __shared__ float wbuf[8];
    int lane = t & 31, wid = t >> 5;
    if (lane == 0) wbuf[wid] = s;
    __syncthreads();
    if (t == 0) {
        float tot = 0.f;
        #pragma unroll
        for (int i = 0; i < 8; i++) tot += wbuf[i];
        wbuf[0] = rsqrtf(tot / (float)DIM + 1e-6f);
    }
    __syncthreads();
    float r = wbuf[0];
    float* xr = g_x + n * DIM;
    for (int c = t; c < DIM; c += 256) xr[c] = row[c] * r * gw[c];
}

// ---------------- tf32x3 tensor-core GEMM ----------------------------------
template <int ACT, int ATOMIC, int RELUA>
__global__ void mma_gemm(const float* __restrict__ A0, const float* __restrict__ A1,
                         const float* __restrict__ B0, const float* __restrict__ B1,
                         const float* __restrict__ bias0, const float* __restrict__ bias1,
                         float* __restrict__ C0, float* __restrict__ C1,
                         int M, int N, int K, int S) {
    __shared__ float As[128][17];
    __shared__ float Bs[16][72];
    int z = blockIdx.z;
    int sel = z / S, sp = z - sel * S;
    const float* A = sel ? A1 : A0;
    const float* B = sel ? B1 : B0;
    const float* bias = sel ? bias1 : bias0;
    float* C = sel ? C1 : C0;
    int Kc = K / S;
    int kb = sp * Kc;

    int tid = threadIdx.x;
    int lane = tid & 31, warp = tid >> 5;
    int wm = warp & 3, wn = warp >> 2;
    int m0 = blockIdx.y * 128, n0 = blockIdx.x * 64;

    float acc[2][4][4];
    #pragma unroll
    for (int i = 0; i < 2; i++)
        #pragma unroll
        for (int j = 0; j < 4; j++)
            #pragma unroll
            for (int l = 0; l < 4; l++) acc[i][j][l] = 0.f;

    for (int k0 = kb; k0 < kb + Kc; k0 += 16) {
        #pragma unroll
        for (int i = 0; i < 2; i++) {
            int q = tid + i * 256;
            int r = q >> 2, c4 = (q & 3) * 4;
            const float4 f = *reinterpret_cast<const float4*>(A + (m0 + r) * K + k0 + c4);
            float4 g = f;
            if (RELUA) {
                g.x = fmaxf(g.x, 0.f); g.y = fmaxf(g.y, 0.f);
                g.z = fmaxf(g.z, 0.f); g.w = fmaxf(g.w, 0.f);
            }
            As[r][c4 + 0] = g.x; As[r][c4 + 1] = g.y;
            As[r][c4 + 2] = g.z; As[r][c4 + 3] = g.w;
        }
        {
            int kr = tid >> 4, nc = (tid & 15) * 4;
            int gn = n0 + nc;
            float4 f = make_float4(0.f, 0.f, 0.f, 0.f);
            if (gn < N) f = *reinterpret_cast<const float4*>(B + (k0 + kr) * N + gn);
            Bs[kr][nc + 0] = f.x; Bs[kr][nc + 1] = f.y;
            Bs[kr][nc + 2] = f.z; Bs[kr][nc + 3] = f.w;
        }
        __syncthreads();
        #pragma unroll
        for (int ks = 0; ks < 2; ks++) {
            int kbase = ks * 8;
            uint32_t ahi[2][4], alo[2][4], bhi[4][2], blo[4][2];
            #pragma unroll
            for (int mt = 0; mt < 2; mt++) {
                int am = wm * 32 + mt * 16 + (lane >> 2);
                int c = kbase + (lane & 3);
                split_tf32(As[am][c],       ahi[mt][0], alo[mt][0]);
                split_tf32(As[am + 8][c],   ahi[mt][1], alo[mt][1]);
                split_tf32(As[am][c + 4],   ahi[mt][2], alo[mt][2]);
                split_tf32(As[am + 8][c + 4], ahi[mt][3], alo[mt][3]);
            }
            #pragma unroll
            for (int nt = 0; nt < 4; nt++) {
                int bn = wn * 32 + nt * 8 + (lane >> 2);
                int r = kbase + (lane & 3);
                split_tf32(Bs[r][bn],     bhi[nt][0], blo[nt][0]);
                split_tf32(Bs[r + 4][bn], bhi[nt][1], blo[nt][1]);
            }
            #pragma unroll
            for (int mt = 0; mt < 2; mt++)
                #pragma unroll
                for (int nt = 0; nt < 4; nt++) {
                    mma_tf32(acc[mt][nt], alo[mt], bhi[nt]);
                    mma_tf32(acc[mt][nt], ahi[mt], blo[nt]);
                    mma_tf32(acc[mt][nt], ahi[mt], bhi[nt]);
                }
        }
        __syncthreads();
    }

    #pragma unroll
    for (int mt = 0; mt < 2; mt++) {
        int row = m0 + wm * 32 + mt * 16 + (lane >> 2);
        #pragma unroll
        for (int nt = 0; nt < 4; nt++) {
            int col = n0 + wn * 32 + nt * 8 + (lane & 3) * 2;
            if (col >= N) continue;
            float* a4 = acc[mt][nt];
            if (ATOMIC) {
                atomicAdd(&C[row * N + col],           a4[0]);
                atomicAdd(&C[row * N + col + 1],       a4[1]);
                atomicAdd(&C[(row + 8) * N + col],     a4[2]);
                atomicAdd(&C[(row + 8) * N + col + 1], a4[3]);
            } else {
                float b0 = bias ? bias[col] : 0.f;
                float b1 = bias ? bias[col + 1] : 0.f;
                float v0 = a4[0] + b0, v1 = a4[1] + b1;
                float v2 = a4[2] + b0, v3 = a4[3] + b1;
                if (ACT == 1) {
                    v0 = fmaxf(v0, 0.f); v1 = fmaxf(v1, 0.f);
                    v2 = fmaxf(v2, 0.f); v3 = fmaxf(v3, 0.f);
                }
                C[row * N + col] = v0;
                C[row * N + col + 1] = v1;
                C[(row + 8) * N + col] = v2;
                C[(row + 8) * N + col + 1] = v3;
            }
        }
    }
}

// ---------------- bias pre-init for split-K atomic targets ------------------
#define SEG1 (128*HID)
#define SEG2 (2*128*HID)
#define SEG3 (SEG2 + 128*DH)
#define SEG4 (SEG2 + 2*128*DH)
#define SEGT (SEG4 + N_SEQ*32)
__global__ void init_bias_kernel(const float* __restrict__ kb1, const float* __restrict__ vb1,
                                 const float* __restrict__ kb2, const float* __restrict__ vb2,
                                 const float* __restrict__ gb) {
    int idx = blockIdx.x * 256 + threadIdx.x;
    if (idx >= SEGT) return;
    if (idx < SEG1)      g_hk[idx] = kb1[idx & (HID - 1)];
    else if (idx < SEG2) g_hv[idx - SEG1] = vb1[idx & (HID - 1)];
    else if (idx < SEG3) g_ckm[idx - SEG2] = kb2[idx & (DH - 1)];
    else if (idx < SEG4) g_cvm[idx - SEG3] = vb2[idx & (DH - 1)];
    else                 g_gates[idx - SEG4] = gb[idx & 31];
}

// ---------------- compressed attention: block per (n, kv), 4 heads ----------
__global__ void cattn_kernel(const float* __restrict__ mem_kv) {
    int n = blockIdx.x, kv = blockIdx.y;
    int t = threadIdx.x;          // 128
    int lane = t & 31, w = t >> 5; // w = head-in-group 0..3
    __shared__ float qs[GQ][64];
    __shared__ float ks[CW][65];
    __shared__ float vs[CW][65];
    __shared__ float ps[GQ][CW];

    // load 4 q heads (pre-rotary)
    qs[w][lane]      = g_qkv[n * QKV_COLS + (kv * GQ + w) * 64 + lane];
    qs[w][lane + 32] = g_qkv[n * QKV_COLS + (kv * GQ + w) * 64 + lane + 32];
    // stage all 33 compressed K and V rows (float4 coalesced per row)
    for (int i = t; i < CW * 16; i += 128) {
        int j = i >> 4, c4 = (i & 15) * 4;
        const float* ksrc = (j == 0) ? (mem_kv + kv * DH)
                                     : (g_ckm + (kv * W_BLK + j - 1) * DH);
        const float* vsrc = (j == 0) ? (mem_kv + KV_HEADS * DH + kv * DH)
                                     : (g_cvm + (kv * W_BLK + j - 1) * DH);
        float4 fk = *reinterpret_cast<const float4*>(ksrc + c4);
        float4 fv = *reinterpret_cast<const float4*>(vsrc + c4);
        ks[j][c4] = fk.x; ks[j][c4+1] = fk.y; ks[j][c4+2] = fk.z; ks[j][c4+3] = fk.w;
        vs[j][c4] = fv.x; vs[j][c4+1] = fv.y; vs[j][c4+2] = fv.z; vs[j][c4+3] = fv.w;
    }
    __syncthreads();

    // sims: warp w = head w; lanes cover keys (j and j+32)
    for (int j = lane; j < CW; j += 32) {
        float acc = 0.f;
        #pragma unroll
        for (int d = 0; d < 64; d++) acc += ks[j][d] * qs[w][d];
        acc *= SCALE;
        ps[w][j] = acc;
        g_csim[((kv * GQ + w) * N_SEQ + n) * CW + j] = acc;
    }
    __syncwarp();
    // softmax per head (warp-local)
    float m = -FLT_MAX;
    for (int j = lane; j < CW; j += 32) m = fmaxf(m, ps[w][j]);
    m = warpMax(m);
    float z = 0.f;
    for (int j = lane; j < CW; j += 32) {
        float e = expf(ps[w][j] - m);
        ps[w][j] = e;
        z += e;
    }
    z = warpSum(z);
    float inv = 1.f / z;
    __syncwarp();
    // output: lanes cover dims (lane, lane+32)
    float acc0 = 0.f, acc1 = 0.f;
    for (int j = 0; j < CW; j++) {
        float p = ps[w][j];
        acc0 += p * vs[j][lane];
        acc1 += p * vs[j][lane + 32];
    }
    int hg = kv * GQ + w;
    g_cout[n * (HEADS * DH) + hg * 64 + lane]      = acc0 * inv;
    g_cout[n * (HEADS * DH) + hg * 64 + lane + 32] = acc1 * inv;
}

// ---------------- rotary in-place on q/k ------------------------------------
__global__ void rotary_kernel() {
    int idx = blockIdx.x * 256 + threadIdx.x;   // < 1024*640
    int n = idx / 640;
    int p = idx - n * 640;
    int col = p * 2;
    int i = (col & 63) >> 1;
    float inv = exp2f(-13.287712379549449f * (float)i / 32.f);
    float ang = (float)n * inv;
    float cs = cosf(ang), sn = sinf(ang);
    float* ptr = g_qkv + n * QKV_COLS + col;
    float x0 = ptr[0], x1 = ptr[1];
    ptr[0] = x0 * cs - x1 * sn;
    ptr[1] = x1 * cs + x0 * sn;
}

// ---------------- top-k block selection -------------------------------------
__global__ void select_kernel() {
    int id = blockIdx.x * 256 + threadIdx.x;
    if (id >= KV_HEADS * N_SEQ) return;
    int kv = id >> 10, n = id & 1023;
    float imp[W_BLK];
    #pragma unroll
    for (int w = 0; w < W_BLK; w++) {
        float s = 0.f;
        #pragma unroll
        for (int g = 0; g < GQ; g++)
            s += g_csim[((kv * GQ + g) * N_SEQ + n) * CW + 1 + w];
        imp[w] = s * 0.25f;
    }
    float m = -1000.f;
    #pragma unroll
    for (int w = 0; w < W_BLK; w++) m = fmaxf(m, imp[w]);
    float Z = expf(-1000.f - m);
    #pragma unroll
    for (int w = 0; w < W_BLK; w++) Z += expf(imp[w] - m);
    int* si = g_selidx + id * NSEL1;
    int* sm = g_selmask + id * NSEL1;
    bool used[W_BLK];
    #pragma unroll
    for (int w = 0; w < W_BLK; w++) used[w] = false;
    for (int s = 0; s < NUM_SEL; s++) {
        int best = -1; float bv = -FLT_MAX;
        for (int w = 0; w < W_BLK; w++)
            if (!used[w] && imp[w] > bv) { bv = imp[w]; best = w; }
        used[best] = true;
        si[s] = best;
        sm[s] = (expf(bv - m) / Z > 1e-10f) ? 1 : 0;
    }
    si[NUM_SEL] = n >> 5;
    sm[NUM_SEL] = 1;
}

// ---------------- fine attention: block per (n, kv), 4 heads, staged --------
__global__ void fattn_kernel() {
    int n = blockIdx.x, kv = blockIdx.y;
    int t = threadIdx.x;           // 256
    int lane = t & 31, w = t >> 5; // 8 warps
    __shared__ float qs[GQ][64];
    __shared__ float stage[BS][65];
    __shared__ float ps[GQ][JTOT];
    __shared__ float pinv[GQ];
    __shared__ int sblk[NSEL1], smk[NSEL1];
    __shared__ float partial[256];

    if (t < 128) {
        int h = t >> 5, l = t & 31;
        qs[h][l]      = g_qkv[n * QKV_COLS + (kv * GQ + h) * 64 + l];
        qs[h][l + 32] = g_qkv[n * QKV_COLS + (kv * GQ + h) * 64 + l + 32];
    }
    if (t < NSEL1) {
        sblk[t] = g_selidx[(kv * N_SEQ + n) * NSEL1 + t];
        smk[t]  = g_selmask[(kv * N_SEQ + n) * NSEL1 + t];
    }
    __syncthreads();

    // phase 1: per selected block, stage K and compute sims for 4 heads
    for (int s = 0; s < NSEL1; s++) {
        int msk = smk[s];
        if (msk) {
            const float* base = g_qkv + (sblk[s] * BS) * QKV_COLS + 1024 + kv * 64;
            for (int i = t; i < 512; i += 256) {
                int r = i >> 4, c4 = (i & 15) * 4;
                float4 f = *reinterpret_cast<const float4*>(base + r * QKV_COLS + c4);
                stage[r][c4] = f.x; stage[r][c4+1] = f.y;
                stage[r][c4+2] = f.z; stage[r][c4+3] = f.w;
            }
        }
        __syncthreads();
        {
            int j = t & 31, h = (t >> 5) & 3, half = t >> 7;
            float acc = 0.f;
            if (msk) {
                int d0 = half * 32;
                #pragma unroll
                for (int d = 0; d < 32; d++) acc += stage[j][d0 + d] * qs[h][d0 + d];
            }
            partial[t] = acc;
        }
        __syncthreads();
        if (t < 128) {
            int j = t & 31, h = t >> 5;
            ps[h][s * BS + j] = msk ? (partial[t] + partial[t + 128]) * SCALE
                                    : -FLT_MAX;
        }
        __syncthreads();
    }

    // phase 2: per-head softmax (warps 0-3)
    if (w < GQ) {
        float m = -FLT_MAX;
        for (int j = lane; j < JTOT; j += 32) m = fmaxf(m, ps[w][j]);
        m = warpMax(m);
        float z = 0.f;
        for (int j = lane; j < JTOT; j += 32) {
            float e = expf(ps[w][j] - m);
            ps[w][j] = e;
            z += e;
        }
        z = warpSum(z);
        if (lane == 0) pinv[w] = 1.f / z;
    }
    __syncthreads();

    // phase 3: stage V per block, accumulate; thread = (head, dim)
    int h = t >> 6, d = t & 63;
    float acc = 0.f;
    for (int s = 0; s < NSEL1; s++) {
        const float* base = g_qkv + (sblk[s] * BS) * QKV_COLS + 1280 + kv * 64;
        for (int i = t; i < 512; i += 256) {
            int r = i >> 4, c4 = (i & 15) * 4;
            float4 f = *reinterpret_cast<const float4*>(base + r * QKV_COLS + c4);
            stage[r][c4] = f.x; stage[r][c4+1] = f.y;
            stage[r][c4+2] = f.z; stage[r][c4+3] = f.w;
        }
        __syncthreads();
        #pragma unroll
        for (int j = 0; j < BS; j++) acc += ps[h][s * BS + j] * stage[j][d];
        __syncthreads();
    }
    g_fout[n * (HEADS * DH) + (kv * GQ + h) * 64 + d] = acc * pinv[h];
}

// ---------------- build kpe / vpe -------------------------------------------
__global__ void build_pe_kernel(const float* __restrict__ k_pos,
                                const float* __restrict__ v_pos) {
    int idx = blockIdx.x * 256 + threadIdx.x;
    int row = idx >> 11;
    int c = idx & 2047;
    int h = row >> 5, w = row & 31;
    int pos = c >> 6, d = c & 63;
    int n = w * BS + pos;
    const float* base = g_qkv + n * QKV_COLS + h * 64 + d;
    g_kpe[idx] = base[1024] + k_pos[(h * BS + pos) * DH + d];
    g_vpe[idx] = base[1280] + v_pos[(h * BS + pos) * DH + d];
}

// ---------------- gated combine ----------------------------------------------
__global__ void combine_kernel() {
    int idx = blockIdx.x * 256 + threadIdx.x;
    int n = idx >> 10;
    int c = idx & 1023;
    int h = c >> 6;
    float r0 = g_gates[n * (2 * HEADS) + 2 * h];
    float r1 = g_gates[n * (2 * HEADS) + 2 * h + 1];
    float g0 = 1.f / (1.f + expf(-r0));
    float g1 = 1.f / (1.f + expf(-r1));
    g_comb[idx] = g0 * g_cout[idx] + g1 * g_fout[idx];
}

// ---------------- launch ------------------------------------------------------
extern "C" void kernel_launch(void* const* d_in, const int* in_sizes, int n_in,
                              void* d_out, int out_size) {
    const float* inp    = (const float*)d_in[0];
    const float* g_norm = (const float*)d_in[1];
    const float* w_qkv  = (const float*)d_in[2];
    const float* mem_kv = (const float*)d_in[3];
    const float* k_pos  = (const float*)d_in[4];
    const float* v_pos  = (const float*)d_in[5];
    const float* k_w1   = (const float*)d_in[6];
    const float* k_b1   = (const float*)d_in[7];
    const float* k_w2   = (const float*)d_in[8];
    const float* k_b2   = (const float*)d_in[9];
    const float* v_w1   = (const float*)d_in[10];
    const float* v_b1   = (const float*)d_in[11];
    const float* v_w2   = (const float*)d_in[12];
    const float* v_b2   = (const float*)d_in[13];
    const float* gate_w = (const float*)d_in[14];
    const float* gate_b = (const float*)d_in[15];
    const float* w_out  = (const float*)d_in[16];
    float* out = (float*)d_out;

    float *px, *pqkv, *pkpe, *pvpe, *phk, *phv, *pckm, *pcvm, *pgates, *pcomb;
    cudaGetSymbolAddress((void**)&px,     g_x);
    cudaGetSymbolAddress((void**)&pqkv,   g_qkv);
    cudaGetSymbolAddress((void**)&pkpe,   g_kpe);
    cudaGetSymbolAddress((void**)&pvpe,   g_vpe);
    cudaGetSymbolAddress((void**)&phk,    g_hk);
    cudaGetSymbolAddress((void**)&phv,    g_hv);
    cudaGetSymbolAddress((void**)&pckm,   g_ckm);
    cudaGetSymbolAddress((void**)&pcvm,   g_cvm);
    cudaGetSymbolAddress((void**)&pgates, g_gates);
    cudaGetSymbolAddress((void**)&pcomb,  g_comb);

    rmsnorm_kernel<<<N_SEQ, 256>>>(inp, g_norm);
    init_bias_kernel<<<(SEGT + 255) / 256, 256>>>(k_b1, v_b1, k_b2, v_b2, gate_b);
    mma_gemm<0, 0, 0><<<dim3(QKV_COLS / 64, N_SEQ / 128, 1), 256>>>(
        px, px, w_qkv, w_qkv, nullptr, nullptr, pqkv, pqkv, N_SEQ, QKV_COLS, DIM, 1);
    build_pe_kernel<<<(KV_HEADS * W_BLK * CDIM) / 256, 256>>>(k_pos, v_pos);
    mma_gemm<0, 1, 0><<<dim3(HID / 64, 1, 2 * 4), 256>>>(
        pkpe, pvpe, k_w1, v_w1, nullptr, nullptr, phk, phv, 128, HID, CDIM, 4);
    mma_gemm<0, 1, 1><<<dim3(1, 1, 2 * 8), 256>>>(
        phk, phv, k_w2, v_w2, nullptr, nullptr, pckm, pcvm, 128, DH, HID, 8);
    cattn_kernel<<<dim3(N_SEQ, KV_HEADS), 128>>>(mem_kv);
    rotary_kernel<<<(N_SEQ * 640) / 256, 256>>>();
    select_kernel<<<(KV_HEADS * N_SEQ) / 256, 256>>>();
    fattn_kernel<<<dim3(N_SEQ, KV_HEADS), 256>>>();
    mma_gemm<0, 1, 0><<<dim3(1, N_SEQ / 128, 4), 256>>>(
        px, px, gate_w, gate_w, nullptr, nullptr, pgates, pgates, N_SEQ, 32, DIM, 4);
    combine_kernel<<<(N_SEQ * HEADS * DH) / 256, 256>>>();
    mma_gemm<0, 0, 0><<<dim3(DIM / 64, N_SEQ / 128, 1), 256>>>(
        pcomb, pcomb, w_out, w_out, nullptr, nullptr, out, out, N_SEQ, DIM, DIM, 1);
}

// round 10
// speedup vs baseline: 3.1972x; 1.1131x over previous
#include <cuda_runtime.h>
#include <math.h>
#include <float.h>
#include <stdint.h>

#define N_SEQ 1024
#define DIM   1024
#define HEADS 16
#define KV_HEADS 4
#define DH    64
#define BS    32
#define NUM_SEL 8
#define W_BLK 32
#define GQ    4
#define CDIM  2048
#define HID   2048
#define QKV_COLS 1536
#define SCALE 0.125f
#define NSEL1 9
#define JTOT  288
#define CW    33

// ---------------- scratch ----------------
__device__ float g_x[N_SEQ*DIM];
__device__ float g_qkv[N_SEQ*QKV_COLS];
__device__ float g_kpe[KV_HEADS*W_BLK*CDIM];
__device__ float g_vpe[KV_HEADS*W_BLK*CDIM];
__device__ float g_hk[KV_HEADS*W_BLK*HID];
__device__ float g_hv[KV_HEADS*W_BLK*HID];
__device__ float g_ckm[KV_HEADS*W_BLK*DH];
__device__ float g_cvm[KV_HEADS*W_BLK*DH];
__device__ float g_csim[HEADS*N_SEQ*CW];
__device__ float g_cout[N_SEQ*HEADS*DH];
__device__ float g_fout[N_SEQ*HEADS*DH];
__device__ int   g_selidx[KV_HEADS*N_SEQ*NSEL1];
__device__ int   g_selmask[KV_HEADS*N_SEQ*NSEL1];
__device__ float g_gates[N_SEQ*2*HEADS];
__device__ float g_comb[N_SEQ*HEADS*DH];

// ---------------- helpers ----------------
__device__ __forceinline__ float warpMax(float v) {
    #pragma unroll
    for (int o = 16; o; o >>= 1) v = fmaxf(v, __shfl_xor_sync(0xffffffffu, v, o));
    return v;
}
__device__ __forceinline__ float warpSum(float v) {
    #pragma unroll
    for (int o = 16; o; o >>= 1) v += __shfl_xor_sync(0xffffffffu, v, o);
    return v;
}
__device__ __forceinline__ uint32_t f2tf32(float f) {
    uint32_t u;
    asm("cvt.rna.tf32.f32 %0, %1;" : "=r"(u) : "f"(f));
    return u;
}
__device__ __forceinline__ void split_tf32(float v, uint32_t& hi, uint32_t& lo) {
    hi = f2tf32(v);
    lo = f2tf32(v - __uint_as_float(hi));
}
__device__ __forceinline__ void mma_tf32(float* c, const uint32_t* a, const uint32_t* b) {
    asm volatile(
        "mma.sync.aligned.m16n8k8.row.col.f32.tf32.tf32.f32 "
        "{%0,%1,%2,%3},{%4,%5,%6,%7},{%8,%9},{%0,%1,%2,%3};"
        : "+f"(c[0]), "+f"(c[1]), "+f"(c[2]), "+f"(c[3])
        : "r"(a[0]), "r"(a[1]), "r"(a[2]), "r"(a[3]), "r"(b[0]), "r"(b[1]));
}
__device__ __forceinline__ void cp16(void* smem_dst, const void* gsrc, int src_size) {
    uint32_t d = (uint32_t)__cvta_generic_to_shared(smem_dst);
    asm volatile("cp.async.ca.shared.global [%0], [%1], 16, %2;"
                 :: "r"(d), "l"(gsrc), "r"(src_size));
}

// ---------------- RMSNorm ----------------
__global__ void rmsnorm_kernel(const float* __restrict__ inp,
                               const float* __restrict__ gw) {
    int n = blockIdx.x;
    int t = threadIdx.x;
    const float* row = inp + n * DIM;
    float s = 0.f;
    for (int c = t; c < DIM; c += 256) { float v = row[c]; s += v * v; }
    s = warpSum(s);
    __shared__ float wbuf[8];
    int lane = t & 31, wid = t >> 5;
    if (lane == 0) wbuf[wid] = s;
    __syncthreads();
    if (t == 0) {
        float tot = 0.f;
        #pragma unroll
        for (int i = 0; i < 8; i++) tot += wbuf[i];
        wbuf[0] = rsqrtf(tot / (float)DIM + 1e-6f);
    }
    __syncthreads();
    float r = wbuf[0];
    float* xr = g_x + n * DIM;
    for (int c = t; c < DIM; c += 256) xr[c] = row[c] * r * gw[c];
}

// ---------------- tf32x3 tensor-core GEMM, cp.async double-buffered ---------
// C = A@B (+bias), A: MxK row-major (M%128==0, K%16==0), B: KxN row-major.
// BM=128, BN=64, BK=16, 256 threads (8 warps, 4Mx2N).
// blockIdx.z = sel*S + split. ATOMIC: atomicAdd into pre-init C.
// RELUA: relu applied to A at fragment load (deferred activation).
template <int ATOMIC, int RELUA>
__global__ void __launch_bounds__(256)
mma_gemm(const float* __restrict__ A0, const float* __restrict__ A1,
         const float* __restrict__ B0, const float* __restrict__ B1,
         const float* __restrict__ bias0, const float* __restrict__ bias1,
         float* __restrict__ C0, float* __restrict__ C1,
         int M, int N, int K, int S) {
    __shared__ float As[2][128][20];
    __shared__ float Bs[2][16][72];
    int z = blockIdx.z;
    int sel = z / S, sp = z - sel * S;
    const float* A = sel ? A1 : A0;
    const float* B = sel ? B1 : B0;
    const float* bias = sel ? bias1 : bias0;
    float* C = sel ? C1 : C0;
    int Kc = K / S;
    int kb = sp * Kc;

    int tid = threadIdx.x;
    int lane = tid & 31, warp = tid >> 5;
    int wm = warp & 3, wn = warp >> 2;
    int m0 = blockIdx.y * 128, n0 = blockIdx.x * 64;

    // precomputed load coordinates
    int ar0 = tid >> 2,          ac0 = (tid & 3) * 4;
    int ar1 = (tid + 256) >> 2,  ac1 = ac0;
    int bkr = tid >> 4,          bnc = (tid & 15) * 4;
    int bgn = n0 + bnc;
    int bsz = (bgn < N) ? 16 : 0;
    const float* bsafe = B;  // fallback ptr when OOB (src_size=0 -> no read)

    float acc[2][4][4];
    #pragma unroll
    for (int i = 0; i < 2; i++)
        #pragma unroll
        for (int j = 0; j < 4; j++)
            #pragma unroll
            for (int l = 0; l < 4; l++) acc[i][j][l] = 0.f;

    int ntiles = Kc / 16;

    // prologue: issue tile 0
    {
        int k0 = kb;
        cp16(&As[0][ar0][ac0], A + (m0 + ar0) * K + k0 + ac0, 16);
        cp16(&As[0][ar1][ac1], A + (m0 + ar1) * K + k0 + ac1, 16);
        cp16(&Bs[0][bkr][bnc], bsz ? (B + (k0 + bkr) * N + bgn) : bsafe, bsz);
        asm volatile("cp.async.commit_group;");
    }

    for (int it = 0; it < ntiles; it++) {
        int buf = it & 1;
        if (it + 1 < ntiles) {
            int k0 = kb + (it + 1) * 16;
            int nb = buf ^ 1;
            cp16(&As[nb][ar0][ac0], A + (m0 + ar0) * K + k0 + ac0, 16);
            cp16(&As[nb][ar1][ac1], A + (m0 + ar1) * K + k0 + ac1, 16);
            cp16(&Bs[nb][bkr][bnc], bsz ? (B + (k0 + bkr) * N + bgn) : bsafe, bsz);
            asm volatile("cp.async.commit_group;");
            asm volatile("cp.async.wait_group 1;");
        } else {
            asm volatile("cp.async.wait_group 0;");
        }
        __syncthreads();

        float (*Asb)[20] = As[buf];
        float (*Bsb)[72] = Bs[buf];
        #pragma unroll
        for (int ks = 0; ks < 2; ks++) {
            int kbase = ks * 8;
            uint32_t ahi[2][4], alo[2][4], bhi[4][2], blo[4][2];
            #pragma unroll
            for (int mt = 0; mt < 2; mt++) {
                int am = wm * 32 + mt * 16 + (lane >> 2);
                int c = kbase + (lane & 3);
                float a0 = Asb[am][c], a1 = Asb[am + 8][c];
                float a2 = Asb[am][c + 4], a3 = Asb[am + 8][c + 4];
                if (RELUA) {
                    a0 = fmaxf(a0, 0.f); a1 = fmaxf(a1, 0.f);
                    a2 = fmaxf(a2, 0.f); a3 = fmaxf(a3, 0.f);
                }
                split_tf32(a0, ahi[mt][0], alo[mt][0]);
                split_tf32(a1, ahi[mt][1], alo[mt][1]);
                split_tf32(a2, ahi[mt][2], alo[mt][2]);
                split_tf32(a3, ahi[mt][3], alo[mt][3]);
            }
            #pragma unroll
            for (int nt = 0; nt < 4; nt++) {
                int bn = wn * 32 + nt * 8 + (lane >> 2);
                int r = kbase + (lane & 3);
                split_tf32(Bsb[r][bn],     bhi[nt][0], blo[nt][0]);
                split_tf32(Bsb[r + 4][bn], bhi[nt][1], blo[nt][1]);
            }
            #pragma unroll
            for (int mt = 0; mt < 2; mt++)
                #pragma unroll
                for (int nt = 0; nt < 4; nt++) {
                    mma_tf32(acc[mt][nt], alo[mt], bhi[nt]);
                    mma_tf32(acc[mt][nt], ahi[mt], blo[nt]);
                    mma_tf32(acc[mt][nt], ahi[mt], bhi[nt]);
                }
        }
        __syncthreads();
    }

    #pragma unroll
    for (int mt = 0; mt < 2; mt++) {
        int row = m0 + wm * 32 + mt * 16 + (lane >> 2);
        #pragma unroll
        for (int nt = 0; nt < 4; nt++) {
            int col = n0 + wn * 32 + nt * 8 + (lane & 3) * 2;
            if (col >= N) continue;
            float* a4 = acc[mt][nt];
            if (ATOMIC) {
                atomicAdd(&C[row * N + col],           a4[0]);
                atomicAdd(&C[row * N + col + 1],       a4[1]);
                atomicAdd(&C[(row + 8) * N + col],     a4[2]);
                atomicAdd(&C[(row + 8) * N + col + 1], a4[3]);
            } else {
                float b0 = bias ? bias[col] : 0.f;
                float b1 = bias ? bias[col + 1] : 0.f;
                C[row * N + col]           = a4[0] + b0;
                C[row * N + col + 1]       = a4[1] + b1;
                C[(row + 8) * N + col]     = a4[2] + b0;
                C[(row + 8) * N + col + 1] = a4[3] + b1;
            }
        }
    }
}

// ---------------- bias pre-init for split-K atomic targets ------------------
#define SEG1 (128*HID)
#define SEG2 (2*128*HID)
#define SEG3 (SEG2 + 128*DH)
#define SEG4 (SEG2 + 2*128*DH)
#define SEGT (SEG4 + N_SEQ*32)
__global__ void init_bias_kernel(const float* __restrict__ kb1, const float* __restrict__ vb1,
                                 const float* __restrict__ kb2, const float* __restrict__ vb2,
                                 const float* __restrict__ gb) {
    int idx = blockIdx.x * 256 + threadIdx.x;
    if (idx >= SEGT) return;
    if (idx < SEG1)      g_hk[idx] = kb1[idx & (HID - 1)];
    else if (idx < SEG2) g_hv[idx - SEG1] = vb1[idx & (HID - 1)];
    else if (idx < SEG3) g_ckm[idx - SEG2] = kb2[idx & (DH - 1)];
    else if (idx < SEG4) g_cvm[idx - SEG3] = vb2[idx & (DH - 1)];
    else                 g_gates[idx - SEG4] = gb[idx & 31];
}

// ---------------- compressed attention: block per (n, kv), 4 heads ----------
__global__ void cattn_kernel(const float* __restrict__ mem_kv) {
    int n = blockIdx.x, kv = blockIdx.y;
    int t = threadIdx.x;
    int lane = t & 31, w = t >> 5;
    __shared__ float qs[GQ][64];
    __shared__ float ks[CW][65];
    __shared__ float vs[CW][65];
    __shared__ float ps[GQ][CW];

    qs[w][lane]      = g_qkv[n * QKV_COLS + (kv * GQ + w) * 64 + lane];
    qs[w][lane + 32] = g_qkv[n * QKV_COLS + (kv * GQ + w) * 64 + lane + 32];
    for (int i = t; i < CW * 16; i += 128) {
        int j = i >> 4, c4 = (i & 15) * 4;
        const float* ksrc = (j == 0) ? (mem_kv + kv * DH)
                                     : (g_ckm + (kv * W_BLK + j - 1) * DH);
        const float* vsrc = (j == 0) ? (mem_kv + KV_HEADS * DH + kv * DH)
                                     : (g_cvm + (kv * W_BLK + j - 1) * DH);
        float4 fk = *reinterpret_cast<const float4*>(ksrc + c4);
        float4 fv = *reinterpret_cast<const float4*>(vsrc + c4);
        ks[j][c4] = fk.x; ks[j][c4+1] = fk.y; ks[j][c4+2] = fk.z; ks[j][c4+3] = fk.w;
        vs[j][c4] = fv.x; vs[j][c4+1] = fv.y; vs[j][c4+2] = fv.z; vs[j][c4+3] = fv.w;
    }
    __syncthreads();

    for (int j = lane; j < CW; j += 32) {
        float acc = 0.f;
        #pragma unroll
        for (int d = 0; d < 64; d++) acc += ks[j][d] * qs[w][d];
        acc *= SCALE;
        ps[w][j] = acc;
        g_csim[((kv * GQ + w) * N_SEQ + n) * CW + j] = acc;
    }
    __syncwarp();
    float m = -FLT_MAX;
    for (int j = lane; j < CW; j += 32) m = fmaxf(m, ps[w][j]);
    m = warpMax(m);
    float z = 0.f;
    for (int j = lane; j < CW; j += 32) {
        float e = expf(ps[w][j] - m);
        ps[w][j] = e;
        z += e;
    }
    z = warpSum(z);
    float inv = 1.f / z;
    __syncwarp();
    float acc0 = 0.f, acc1 = 0.f;
    for (int j = 0; j < CW; j++) {
        float p = ps[w][j];
        acc0 += p * vs[j][lane];
        acc1 += p * vs[j][lane + 32];
    }
    int hg = kv * GQ + w;
    g_cout[n * (HEADS * DH) + hg * 64 + lane]      = acc0 * inv;
    g_cout[n * (HEADS * DH) + hg * 64 + lane + 32] = acc1 * inv;
}

// ---------------- rotary in-place on q/k ------------------------------------
__global__ void rotary_kernel() {
    int idx = blockIdx.x * 256 + threadIdx.x;
    int n = idx / 640;
    int p = idx - n * 640;
    int col = p * 2;
    int i = (col & 63) >> 1;
    float inv = exp2f(-13.287712379549449f * (float)i / 32.f);
    float ang = (float)n * inv;
    float cs = cosf(ang), sn = sinf(ang);
    float* ptr = g_qkv + n * QKV_COLS + col;
    float x0 = ptr[0], x1 = ptr[1];
    ptr[0] = x0 * cs - x1 * sn;
    ptr[1] = x1 * cs + x0 * sn;
}

// ---------------- top-k block selection -------------------------------------
__global__ void select_kernel() {
    int id = blockIdx.x * 256 + threadIdx.x;
    if (id >= KV_HEADS * N_SEQ) return;
    int kv = id >> 10, n = id & 1023;
    float imp[W_BLK];
    #pragma unroll
    for (int w = 0; w < W_BLK; w++) {
        float s = 0.f;
        #pragma unroll
        for (int g = 0; g < GQ; g++)
            s += g_csim[((kv * GQ + g) * N_SEQ + n) * CW + 1 + w];
        imp[w] = s * 0.25f;
    }
    float m = -1000.f;
    #pragma unroll
    for (int w = 0; w < W_BLK; w++) m = fmaxf(m, imp[w]);
    float Z = expf(-1000.f - m);
    #pragma unroll
    for (int w = 0; w < W_BLK; w++) Z += expf(imp[w] - m);
    int* si = g_selidx + id * NSEL1;
    int* sm = g_selmask + id * NSEL1;
    bool used[W_BLK];
    #pragma unroll
    for (int w = 0; w < W_BLK; w++) used[w] = false;
    for (int s = 0; s < NUM_SEL; s++) {
        int best = -1; float bv = -FLT_MAX;
        for (int w = 0; w < W_BLK; w++)
            if (!used[w] && imp[w] > bv) { bv = imp[w]; best = w; }
        used[best] = true;
        si[s] = best;
        sm[s] = (expf(bv - m) / Z > 1e-10f) ? 1 : 0;
    }
    si[NUM_SEL] = n >> 5;
    sm[NUM_SEL] = 1;
}

// ---------------- fine attention: block per (n, kv), 4 heads, staged --------
__global__ void fattn_kernel() {
    int n = blockIdx.x, kv = blockIdx.y;
    int t = threadIdx.x;
    int lane = t & 31, w = t >> 5;
    __shared__ float qs[GQ][64];
    __shared__ float stage[BS][65];
    __shared__ float ps[GQ][JTOT];
    __shared__ float pinv[GQ];
    __shared__ int sblk[NSEL1], smk[NSEL1];
    __shared__ float partial[256];

    if (t < 128) {
        int h = t >> 5, l = t & 31;
        qs[h][l]      = g_qkv[n * QKV_COLS + (kv * GQ + h) * 64 + l];
        qs[h][l + 32] = g_qkv[n * QKV_COLS + (kv * GQ + h) * 64 + l + 32];
    }
    if (t < NSEL1) {
        sblk[t] = g_selidx[(kv * N_SEQ + n) * NSEL1 + t];
        smk[t]  = g_selmask[(kv * N_SEQ + n) * NSEL1 + t];
    }
    __syncthreads();

    for (int s = 0; s < NSEL1; s++) {
        int msk = smk[s];
        if (msk) {
            const float* base = g_qkv + (sblk[s] * BS) * QKV_COLS + 1024 + kv * 64;
            for (int i = t; i < 512; i += 256) {
                int r = i >> 4, c4 = (i & 15) * 4;
                float4 f = *reinterpret_cast<const float4*>(base + r * QKV_COLS + c4);
                stage[r][c4] = f.x; stage[r][c4+1] = f.y;
                stage[r][c4+2] = f.z; stage[r][c4+3] = f.w;
            }
        }
        __syncthreads();
        {
            int j = t & 31, h = (t >> 5) & 3, half = t >> 7;
            float acc = 0.f;
            if (msk) {
                int d0 = half * 32;
                #pragma unroll
                for (int d = 0; d < 32; d++) acc += stage[j][d0 + d] * qs[h][d0 + d];
            }
            partial[t] = acc;
        }
        __syncthreads();
        if (t < 128) {
            int j = t & 31, h = t >> 5;
            ps[h][s * BS + j] = msk ? (partial[t] + partial[t + 128]) * SCALE
                                    : -FLT_MAX;
        }
        __syncthreads();
    }

    if (w < GQ) {
        float m = -FLT_MAX;
        for (int j = lane; j < JTOT; j += 32) m = fmaxf(m, ps[w][j]);
        m = warpMax(m);
        float z = 0.f;
        for (int j = lane; j < JTOT; j += 32) {
            float e = expf(ps[w][j] - m);
            ps[w][j] = e;
            z += e;
        }
        z = warpSum(z);
        if (lane == 0) pinv[w] = 1.f / z;
    }
    __syncthreads();

    int h = t >> 6, d = t & 63;
    float acc = 0.f;
    for (int s = 0; s < NSEL1; s++) {
        const float* base = g_qkv + (sblk[s] * BS) * QKV_COLS + 1280 + kv * 64;
        for (int i = t; i < 512; i += 256) {
            int r = i >> 4, c4 = (i & 15) * 4;
            float4 f = *reinterpret_cast<const float4*>(base + r * QKV_COLS + c4);
            stage[r][c4] = f.x; stage[r][c4+1] = f.y;
            stage[r][c4+2] = f.z; stage[r][c4+3] = f.w;
        }
        __syncthreads();
        #pragma unroll
        for (int j = 0; j < BS; j++) acc += ps[h][s * BS + j] * stage[j][d];
        __syncthreads();
    }
    g_fout[n * (HEADS * DH) + (kv * GQ + h) * 64 + d] = acc * pinv[h];
}

// ---------------- build kpe / vpe -------------------------------------------
__global__ void build_pe_kernel(const float* __restrict__ k_pos,
                                const float* __restrict__ v_pos) {
    int idx = blockIdx.x * 256 + threadIdx.x;
    int row = idx >> 11;
    int c = idx & 2047;
    int h = row >> 5, w = row & 31;
    int pos = c >> 6, d = c & 63;
    int n = w * BS + pos;
    const float* base = g_qkv + n * QKV_COLS + h * 64 + d;
    g_kpe[idx] = base[1024] + k_pos[(h * BS + pos) * DH + d];
    g_vpe[idx] = base[1280] + v_pos[(h * BS + pos) * DH + d];
}

// ---------------- gated combine ----------------------------------------------
__global__ void combine_kernel() {
    int idx = blockIdx.x * 256 + threadIdx.x;
    int n = idx >> 10;
    int c = idx & 1023;
    int h = c >> 6;
    float r0 = g_gates[n * (2 * HEADS) + 2 * h];
    float r1 = g_gates[n * (2 * HEADS) + 2 * h + 1];
    float g0 = 1.f / (1.f + expf(-r0));
    float g1 = 1.f / (1.f + expf(-r1));
    g_comb[idx] = g0 * g_cout[idx] + g1 * g_fout[idx];
}

// ---------------- launch ------------------------------------------------------
extern "C" void kernel_launch(void* const* d_in, const int* in_sizes, int n_in,
                              void* d_out, int out_size) {
    const float* inp    = (const float*)d_in[0];
    const float* g_norm = (const float*)d_in[1];
    const float* w_qkv  = (const float*)d_in[2];
    const float* mem_kv = (const float*)d_in[3];
    const float* k_pos  = (const float*)d_in[4];
    const float* v_pos  = (const float*)d_in[5];
    const float* k_w1   = (const float*)d_in[6];
    const float* k_b1   = (const float*)d_in[7];
    const float* k_w2   = (const float*)d_in[8];
    const float* k_b2   = (const float*)d_in[9];
    const float* v_w1   = (const float*)d_in[10];
    const float* v_b1   = (const float*)d_in[11];
    const float* v_w2   = (const float*)d_in[12];
    const float* v_b2   = (const float*)d_in[13];
    const float* gate_w = (const float*)d_in[14];
    const float* gate_b = (const float*)d_in[15];
    const float* w_out  = (const float*)d_in[16];
    float* out = (float*)d_out;

    float *px, *pqkv, *pkpe, *pvpe, *phk, *phv, *pckm, *pcvm, *pgates, *pcomb;
    cudaGetSymbolAddress((void**)&px,     g_x);
    cudaGetSymbolAddress((void**)&pqkv,   g_qkv);
    cudaGetSymbolAddress((void**)&pkpe,   g_kpe);
    cudaGetSymbolAddress((void**)&pvpe,   g_vpe);
    cudaGetSymbolAddress((void**)&phk,    g_hk);
    cudaGetSymbolAddress((void**)&phv,    g_hv);
    cudaGetSymbolAddress((void**)&pckm,   g_ckm);
    cudaGetSymbolAddress((void**)&pcvm,   g_cvm);
    cudaGetSymbolAddress((void**)&pgates, g_gates);
    cudaGetSymbolAddress((void**)&pcomb,  g_comb);

    rmsnorm_kernel<<<N_SEQ, 256>>>(inp, g_norm);
    init_bias_kernel<<<(SEGT + 255) / 256, 256>>>(k_b1, v_b1, k_b2, v_b2, gate_b);
    mma_gemm<0, 0><<<dim3(QKV_COLS / 64, N_SEQ / 128, 1), 256>>>(
        px, px, w_qkv, w_qkv, nullptr, nullptr, pqkv, pqkv, N_SEQ, QKV_COLS, DIM, 1);
    build_pe_kernel<<<(KV_HEADS * W_BLK * CDIM) / 256, 256>>>(k_pos, v_pos);
    mma_gemm<1, 0><<<dim3(HID / 64, 1, 2 * 4), 256>>>(
        pkpe, pvpe, k_w1, v_w1, nullptr, nullptr, phk, phv, 128, HID, CDIM, 4);
    mma_gemm<1, 1><<<dim3(1, 1, 2 * 8), 256>>>(
        phk, phv, k_w2, v_w2, nullptr, nullptr, pckm, pcvm, 128, DH, HID, 8);
    cattn_kernel<<<dim3(N_SEQ, KV_HEADS), 128>>>(mem_kv);
    rotary_kernel<<<(N_SEQ * 640) / 256, 256>>>();
    select_kernel<<<(KV_HEADS * N_SEQ) / 256, 256>>>();
    fattn_kernel<<<dim3(N_SEQ, KV_HEADS), 256>>>();
    mma_gemm<1, 0><<<dim3(1, N_SEQ / 128, 4), 256>>>(
        px, px, gate_w, gate_w, nullptr, nullptr, pgates, pgates, N_SEQ, 32, DIM, 4);
    combine_kernel<<<(N_SEQ * HEADS * DH) / 256, 256>>>();
    mma_gemm<0, 0><<<dim3(DIM / 64, N_SEQ / 128, 1), 256>>>(
        pcomb, pcomb, w_out, w_out, nullptr, nullptr, out, out, N_SEQ, DIM, DIM, 1);
}